// round 12
// baseline (speedup 1.0000x reference)
#include <cuda_runtime.h>
#include <math.h>
#include <stdint.h>

// Problem constants
#define BB   2
#define NQ   2048
#define DD   256
#define HH   8
#define DH   32
#define LK   4096      // M*NN
#define NNK  2048
#define KNN  8
#define NSETS 6

static __device__ __forceinline__ uint32_t f2tf32(float x) {
    uint32_t u;
    asm("cvt.rna.tf32.f32 %0, %1;" : "=r"(u) : "f"(x));
    return u;
}
// pack {lo, hi} floats into f16x2 (lo -> bits[0:16])
static __device__ __forceinline__ uint32_t pk_f16x2(float lo, float hi) {
    uint32_t d;
    asm("cvt.rn.f16x2.f32 %0, %1, %2;" : "=r"(d) : "f"(hi), "f"(lo));
    return d;
}
// 2^x elementwise on f16x2
static __device__ __forceinline__ uint32_t ex2_f16x2(uint32_t x) {
    uint32_t d;
    asm("ex2.approx.f16x2 %0, %1;" : "=r"(d) : "r"(x));
    return d;
}
static __device__ __forceinline__ uint32_t prmt(uint32_t a, uint32_t b, uint32_t s) {
    uint32_t d;
    asm("prmt.b32 %0, %1, %2, %3;" : "=r"(d) : "r"(a), "r"(b), "r"(s));
    return d;
}

// m16n8k8 tf32 mma (projection kernels)
static __device__ __forceinline__ void mma_tf32(float& d0, float& d1, float& d2, float& d3,
                                                uint32_t a0, uint32_t a1, uint32_t a2, uint32_t a3,
                                                uint32_t b0, uint32_t b1)
{
    asm volatile(
        "mma.sync.aligned.m16n8k8.row.col.f32.tf32.tf32.f32 "
        "{%0,%1,%2,%3}, {%4,%5,%6,%7}, {%8,%9}, {%0,%1,%2,%3};"
        : "+f"(d0), "+f"(d1), "+f"(d2), "+f"(d3)
        : "r"(a0), "r"(a1), "r"(a2), "r"(a3), "r"(b0), "r"(b1));
}

// m16n8k16 f16 mma (f32 accum)
static __device__ __forceinline__ void mma_f16(float& d0, float& d1, float& d2, float& d3,
                                               uint32_t a0, uint32_t a1, uint32_t a2, uint32_t a3,
                                               uint32_t b0, uint32_t b1)
{
    asm volatile(
        "mma.sync.aligned.m16n8k16.row.col.f32.f16.f16.f32 "
        "{%0,%1,%2,%3}, {%4,%5,%6,%7}, {%8,%9}, {%0,%1,%2,%3};"
        : "+f"(d0), "+f"(d1), "+f"(d2), "+f"(d3)
        : "r"(a0), "r"(a1), "r"(a2), "r"(a3), "r"(b0), "r"(b1));
}

#define ONESH2 0x3C003C00u   // f16x2 {1.0, 1.0}

// ---------------- scratch ----------------
__device__ float    g_cur_edge[BB * NQ * DD];
__device__ float    g_all_nbr [BB * LK * DD];
__device__ uint32_t g_q   [BB * NQ * DD / 2];    // f16x2 packed (pre-scaled)
__device__ uint32_t g_k   [BB * LK * DD / 2];
__device__ uint32_t g_v   [BB * LK * DD / 2];
__device__ float    g_attn[BB * NQ * DD];

// =====================================================================
// Kernel 1: FUSED KNN top-8 + edge features
// grid (16, 6), block 128. Phase 1: each thread finds top-8 for its row.
// Phase 2: idx via smem; 8 threads/row x 32-float segments, coalesced
// gathers (all feature sets are L2-resident).
// =====================================================================
__global__ void __launch_bounds__(128, 1)
knn_edge_kernel(const float* __restrict__ cur_pts,
                const float* __restrict__ nbr_pts,
                const float* __restrict__ cur_f,
                const float* __restrict__ nbr_f)
{
    int set = blockIdx.y;
    const float* pts = (set < 2) ? (cur_pts + (size_t)set * NQ * 3)
                                 : (nbr_pts + (size_t)(set - 2) * NNK * 3);
    __shared__ float px[2048], py[2048], pz[2048], sq[2048];
    __shared__ int   sidx[128 * KNN];

    int tid = threadIdx.x;
    for (int i = tid; i < 2048; i += blockDim.x) {
        float x = pts[i * 3 + 0], y = pts[i * 3 + 1], z = pts[i * 3 + 2];
        px[i] = x; py[i] = y; pz[i] = z;
        sq[i] = x * x + y * y + z * z;
    }
    __syncthreads();

    int rowbase = blockIdx.x * 128;
    int row = rowbase + tid;
    float bx = px[row & 2047], by = py[row & 2047], bz = pz[row & 2047], bsq = sq[row & 2047];

    float bestd[KNN];
    int   besti[KNN];
#pragma unroll
    for (int t = 0; t < KNN; t++) { bestd[t] = INFINITY; besti[t] = -1; }

    for (int j0 = 0; j0 < 2048; j0 += 4) {
        float d2v[4];
#pragma unroll
        for (int u = 0; u < 4; u++) {
            int jj = j0 + u;
            float dot = bx * px[jj] + by * py[jj] + bz * pz[jj];
            d2v[u] = bsq + sq[jj] - 2.0f * dot;
        }
#pragma unroll
        for (int u = 0; u < 4; u++) {
            float d2 = d2v[u];
            if (d2 < bestd[KNN - 1]) {
                int t = KNN - 1;
#pragma unroll
                for (int w = KNN - 1; w > 0; w--) {
                    if (bestd[w - 1] > d2) { bestd[w] = bestd[w - 1]; besti[w] = besti[w - 1]; t = w - 1; }
                    else break;
                }
                bestd[t] = d2; besti[t] = j0 + u;
            }
        }
    }

#pragma unroll
    for (int t = 0; t < KNN; t++) sidx[tid * KNN + t] = besti[t];
    __syncthreads();

    // ---- Phase 2: edge = f - mean(f[knn]) ----
    const float* f;
    float* outbase;
    if (set < 2) {
        f       = cur_f + (size_t)set * NQ * DD;
        outbase = g_cur_edge + (size_t)set * NQ * DD;
    } else {
        int mb = set - 2;              // m*B + b
        int m = mb >> 1, b = mb & 1;
        f       = nbr_f + (size_t)mb * NNK * DD;
        outbase = g_all_nbr + ((size_t)b * LK + (size_t)m * NNK) * DD;
    }

    int rsub = tid >> 3;               // 0..15 (row within 16-row group)
    int dseg = (tid & 7) * 32;         // 32-float segment

#pragma unroll 1
    for (int rr = 0; rr < 8; rr++) {
        int lr = rr * 16 + rsub;       // local row 0..127
        int grow = rowbase + lr;
        int idx[KNN];
#pragma unroll
        for (int t = 0; t < KNN; t++) idx[t] = sidx[lr * KNN + t];

        const float* selfp = f + (size_t)grow * DD + dseg;
        float* outp = outbase + (size_t)grow * DD + dseg;

#pragma unroll
        for (int q = 0; q < 8; q++) {
            float4 acc = make_float4(0.f, 0.f, 0.f, 0.f);
#pragma unroll
            for (int t = 0; t < KNN; t++) {
                float4 v = *(const float4*)&f[(size_t)idx[t] * DD + dseg + q * 4];
                acc.x += v.x; acc.y += v.y; acc.z += v.z; acc.w += v.w;
            }
            float4 s = *(const float4*)&selfp[q * 4];
            float4 o;
            o.x = s.x - acc.x * 0.125f;
            o.y = s.y - acc.y * 0.125f;
            o.z = s.z - acc.z * 0.125f;
            o.w = s.w - acc.w * 0.125f;
            *(float4*)&outp[q * 4] = o;
        }
    }
    __syncthreads();

    // second half of rows (rows 128*bx .. : rr covered 0..7 => 128 rows? )
    // NOTE: rr loop above covers lr = 0..127 via rr*16+rsub with rr<8, rsub<16. Done.
}

// =====================================================================
// Kernel 3: projection GEMM on tensor pipe (m16n8k8 tf32)
// (unchanged — validated)
// =====================================================================
#define PSTR 36
#define PROJ_SMEM_FLOATS (2 * 128 * PSTR + 2 * 64 * PSTR)
#define PSM_A(buf) ((buf) * (128 * PSTR))
#define PSM_W(buf) (2 * 128 * PSTR + (buf) * (64 * PSTR))

__global__ void __launch_bounds__(256, 2)
gemm_proj_mma(const float* __restrict__ A,
              const float* __restrict__ W,
              const float* __restrict__ bias,
              float* __restrict__ C,
              int out_half,
              float oscale,
              const float* __restrict__ pts,   // may be null
              const float* __restrict__ sw,
              const float* __restrict__ sb)
{
    extern __shared__ float psm[];

    int tid = threadIdx.x;
    int wid = tid >> 5, lane = tid & 31;
    int g = lane >> 2, j = lane & 3;
    int wm = wid >> 1, wn = wid & 1;
    int m0 = blockIdx.x * 128;
    int n0 = blockIdx.y * 64;

    int ar[4], ac[4];
#pragma unroll
    for (int u = 0; u < 4; u++) {
        int fid = tid + 256 * u;
        ar[u] = fid >> 3;  ac[u] = (fid & 7) * 4;
    }
    int wr[2], wc[2];
#pragma unroll
    for (int u = 0; u < 2; u++) {
        int fid = tid + 256 * u;
        wr[u] = fid >> 3;  wc[u] = (fid & 7) * 4;
    }

    const float* Ab = A + (size_t)m0 * 256;
    const float* Wb = W + (size_t)n0 * 256;

    float acc[2][4][4];
#pragma unroll
    for (int i = 0; i < 2; i++)
#pragma unroll
        for (int n = 0; n < 4; n++)
#pragma unroll
            for (int r = 0; r < 4; r++) acc[i][n][r] = 0.0f;

    float4 apre[4], wpre[2];
#pragma unroll
    for (int u = 0; u < 4; u++) apre[u] = *(const float4*)&Ab[(size_t)ar[u] * 256 + ac[u]];
#pragma unroll
    for (int u = 0; u < 2; u++) wpre[u] = *(const float4*)&Wb[(size_t)wr[u] * 256 + wc[u]];
#pragma unroll
    for (int u = 0; u < 4; u++) {
        uint4 t;
        t.x = f2tf32(apre[u].x); t.y = f2tf32(apre[u].y);
        t.z = f2tf32(apre[u].z); t.w = f2tf32(apre[u].w);
        *(uint4*)&psm[PSM_A(0) + ar[u] * PSTR + ac[u]] = t;
    }
#pragma unroll
    for (int u = 0; u < 2; u++) {
        uint4 t;
        t.x = f2tf32(wpre[u].x); t.y = f2tf32(wpre[u].y);
        t.z = f2tf32(wpre[u].z); t.w = f2tf32(wpre[u].w);
        *(uint4*)&psm[PSM_W(0) + wr[u] * PSTR + wc[u]] = t;
    }

    for (int it = 0; it < 8; it++) {
        int s = it & 1;
        if (it < 7) {
            int ko = (it + 1) * 32;
#pragma unroll
            for (int u = 0; u < 4; u++) apre[u] = *(const float4*)&Ab[(size_t)ar[u] * 256 + ko + ac[u]];
#pragma unroll
            for (int u = 0; u < 2; u++) wpre[u] = *(const float4*)&Wb[(size_t)wr[u] * 256 + ko + wc[u]];
        }
        __syncthreads();
        if (it < 7) {
#pragma unroll
            for (int u = 0; u < 4; u++) {
                uint4 t;
                t.x = f2tf32(apre[u].x); t.y = f2tf32(apre[u].y);
                t.z = f2tf32(apre[u].z); t.w = f2tf32(apre[u].w);
                *(uint4*)&psm[PSM_A(1 - s) + ar[u] * PSTR + ac[u]] = t;
            }
#pragma unroll
            for (int u = 0; u < 2; u++) {
                uint4 t;
                t.x = f2tf32(wpre[u].x); t.y = f2tf32(wpre[u].y);
                t.z = f2tf32(wpre[u].z); t.w = f2tf32(wpre[u].w);
                *(uint4*)&psm[PSM_W(1 - s) + wr[u] * PSTR + wc[u]] = t;
            }
        }

        const uint32_t* As = (const uint32_t*)&psm[PSM_A(s)];
        const uint32_t* Ws = (const uint32_t*)&psm[PSM_W(s)];

#pragma unroll
        for (int kt = 0; kt < 4; kt++) {
            uint32_t af[2][4];
#pragma unroll
            for (int i = 0; i < 2; i++) {
                int rb = wm * 32 + i * 16;
                af[i][0] = As[(rb + g)     * PSTR + kt * 8 + j];
                af[i][1] = As[(rb + g + 8) * PSTR + kt * 8 + j];
                af[i][2] = As[(rb + g)     * PSTR + kt * 8 + j + 4];
                af[i][3] = As[(rb + g + 8) * PSTR + kt * 8 + j + 4];
            }
#pragma unroll
            for (int n = 0; n < 4; n++) {
                int nb = wn * 32 + n * 8;
                uint32_t b0 = Ws[(nb + g) * PSTR + kt * 8 + j];
                uint32_t b1 = Ws[(nb + g) * PSTR + kt * 8 + j + 4];
#pragma unroll
                for (int i = 0; i < 2; i++)
                    mma_tf32(acc[i][n][0], acc[i][n][1], acc[i][n][2], acc[i][n][3],
                             af[i][0], af[i][1], af[i][2], af[i][3], b0, b1);
            }
        }
    }

#pragma unroll
    for (int i = 0; i < 2; i++) {
        int r_lo = m0 + wm * 32 + i * 16 + g;
        float p0a = 0.f, p1a = 0.f, p2a = 0.f, p0b = 0.f, p1b = 0.f, p2b = 0.f;
        if (pts) {
            p0a = pts[r_lo * 3 + 0]; p1a = pts[r_lo * 3 + 1]; p2a = pts[r_lo * 3 + 2];
            p0b = pts[(r_lo + 8) * 3 + 0]; p1b = pts[(r_lo + 8) * 3 + 1]; p2b = pts[(r_lo + 8) * 3 + 2];
        }
#pragma unroll
        for (int n = 0; n < 4; n++) {
            int col = n0 + wn * 32 + n * 8 + 2 * j;
            float b0 = bias[col], b1 = bias[col + 1];
            float v00 = acc[i][n][0] + b0, v01 = acc[i][n][1] + b1;
            float v10 = acc[i][n][2] + b0, v11 = acc[i][n][3] + b1;
            if (pts) {
                float s0 = sw[col * 3], s1 = sw[col * 3 + 1], s2 = sw[col * 3 + 2];
                float t0 = sw[(col+1) * 3], t1 = sw[(col+1) * 3 + 1], t2 = sw[(col+1) * 3 + 2];
                v00 += p0a * s0 + p1a * s1 + p2a * s2 + sb[col];
                v01 += p0a * t0 + p1a * t1 + p2a * t2 + sb[col + 1];
                v10 += p0b * s0 + p1b * s1 + p2b * s2 + sb[col];
                v11 += p0b * t0 + p1b * t1 + p2b * t2 + sb[col + 1];
            }
            if (out_half) {
                uint32_t* Cu = (uint32_t*)C;
                Cu[(size_t)r_lo * 128 + (col >> 1)]       = pk_f16x2(v00 * oscale, v01 * oscale);
                Cu[(size_t)(r_lo + 8) * 128 + (col >> 1)] = pk_f16x2(v10 * oscale, v11 * oscale);
            } else {
                *(float2*)&C[(size_t)r_lo * 256 + col]       = make_float2(v00, v01);
                *(float2*)&C[(size_t)(r_lo + 8) * 256 + col] = make_float2(v10, v11);
            }
        }
    }
}

// =====================================================================
// Kernel 4: flash attention — ROUND-10 CONFIG (best known):
// fp16 MMA; 4 warps x 32 q-rows (two m16 A-tiles/warp, LDS/MMA = 1),
// q-tile 128, grid (16,16), occ 3.
// P = 2^S via ex2.f16x2 (scale folded into Q); row sums via ones-MMA.
// =====================================================================
#define KV32 20
#define VV32 40
#define SMEM_K_OFF(buf) ((buf) * (128 * KV32))
#define SMEM_V_OFF(buf) (2 * 128 * KV32 + (buf) * (64 * VV32))
#define FLASH_SMEM_U32 (2 * 128 * KV32 + 2 * 64 * VV32)

__global__ void __launch_bounds__(128, 3)
flash_mma_kernel(const uint32_t* __restrict__ Q, const uint32_t* __restrict__ K,
                 const uint32_t* __restrict__ V, float* __restrict__ O)
{
    extern __shared__ uint32_t smu[];

    int tid = threadIdx.x;
    int wid = tid >> 5, lane = tid & 31;
    int g = lane >> 2, j = lane & 3;
    int q0 = blockIdx.x * 128;
    int bh = blockIdx.y, b = bh >> 3, h = bh & 7;

    const uint32_t* qp = Q + ((size_t)b * NQ + q0 + wid * 32) * 128 + h * 16;
    const uint32_t* kp = K + (size_t)b * LK * 128 + h * 16;
    const uint32_t* vp = V + (size_t)b * LK * 128 + h * 16;

    uint32_t aq[2][2][4];
#pragma unroll
    for (int i = 0; i < 2; i++)
#pragma unroll
        for (int kt = 0; kt < 2; kt++) {
            int rb = i * 16;
            aq[i][kt][0] = qp[(size_t)(rb + g) * 128 + kt * 8 + j];
            aq[i][kt][1] = qp[(size_t)(rb + g + 8) * 128 + kt * 8 + j];
            aq[i][kt][2] = qp[(size_t)(rb + g) * 128 + kt * 8 + j + 4];
            aq[i][kt][3] = qp[(size_t)(rb + g + 8) * 128 + kt * 8 + j + 4];
        }

    float o[2][4][4];
#pragma unroll
    for (int i = 0; i < 2; i++)
#pragma unroll
        for (int n = 0; n < 4; n++)
#pragma unroll
            for (int r = 0; r < 4; r++) o[i][n][r] = 0.0f;
    float lacc[2][4] = {{0,0,0,0},{0,0,0,0}};

    int krow[4], kq4[4];
#pragma unroll
    for (int u = 0; u < 4; u++) {
        int fid = tid + 128 * u;
        krow[u] = fid >> 2;
        kq4[u]  = (fid & 3) * 4;
    }
    int vpi[2], vqq[2];
#pragma unroll
    for (int u = 0; u < 2; u++) {
        int fid = tid + 128 * u;
        vpi[u] = fid >> 2;
        vqq[u] = (fid & 3) * 4;
    }

    uint4 kpre[4], ve[2], vo[2];
#pragma unroll
    for (int u = 0; u < 4; u++)
        kpre[u] = *(const uint4*)&kp[(size_t)krow[u] * 128 + kq4[u]];
#pragma unroll
    for (int u = 0; u < 2; u++) {
        ve[u] = *(const uint4*)&vp[(size_t)(2 * vpi[u]) * 128 + vqq[u]];
        vo[u] = *(const uint4*)&vp[(size_t)(2 * vpi[u] + 1) * 128 + vqq[u]];
    }
#pragma unroll
    for (int u = 0; u < 4; u++)
        *(uint4*)&smu[SMEM_K_OFF(0) + krow[u] * KV32 + kq4[u]] = kpre[u];
#pragma unroll
    for (int u = 0; u < 2; u++) {
        uint4 w0, w1;
        w0.x = prmt(ve[u].x, vo[u].x, 0x5410); w0.y = prmt(ve[u].x, vo[u].x, 0x7632);
        w0.z = prmt(ve[u].y, vo[u].y, 0x5410); w0.w = prmt(ve[u].y, vo[u].y, 0x7632);
        w1.x = prmt(ve[u].z, vo[u].z, 0x5410); w1.y = prmt(ve[u].z, vo[u].z, 0x7632);
        w1.z = prmt(ve[u].w, vo[u].w, 0x5410); w1.w = prmt(ve[u].w, vo[u].w, 0x7632);
        *(uint4*)&smu[SMEM_V_OFF(0) + vpi[u] * VV32 + vqq[u] * 2]     = w0;
        *(uint4*)&smu[SMEM_V_OFF(0) + vpi[u] * VV32 + vqq[u] * 2 + 4] = w1;
    }

    for (int c = 0; c < 32; c++) {
        int buf = c & 1;
        if (c < 31) {
            int kb = (c + 1) * 128;
#pragma unroll
            for (int u = 0; u < 4; u++)
                kpre[u] = *(const uint4*)&kp[(size_t)(kb + krow[u]) * 128 + kq4[u]];
#pragma unroll
            for (int u = 0; u < 2; u++) {
                ve[u] = *(const uint4*)&vp[(size_t)(kb + 2 * vpi[u]) * 128 + vqq[u]];
                vo[u] = *(const uint4*)&vp[(size_t)(kb + 2 * vpi[u] + 1) * 128 + vqq[u]];
            }
        }
        __syncthreads();

        const uint32_t* Ks = &smu[SMEM_K_OFF(buf)];
        const uint32_t* Vs = &smu[SMEM_V_OFF(buf)];

#pragma unroll
        for (int qq = 0; qq < 4; qq++) {
            float s[2][4][4];
#pragma unroll
            for (int i = 0; i < 2; i++)
#pragma unroll
                for (int nt = 0; nt < 4; nt++)
#pragma unroll
                    for (int r = 0; r < 4; r++) s[i][nt][r] = 0.0f;

#pragma unroll
            for (int kt = 0; kt < 2; kt++) {
#pragma unroll
                for (int nt = 0; nt < 4; nt++) {
                    int kvrow = qq * 32 + nt * 8 + g;
                    uint32_t b0 = Ks[kvrow * KV32 + kt * 8 + j];
                    uint32_t b1 = Ks[kvrow * KV32 + kt * 8 + j + 4];
#pragma unroll
                    for (int i = 0; i < 2; i++)
                        mma_f16(s[i][nt][0], s[i][nt][1], s[i][nt][2], s[i][nt][3],
                                aq[i][kt][0], aq[i][kt][1], aq[i][kt][2], aq[i][kt][3],
                                b0, b1);
                }
            }

#pragma unroll
            for (int t = 0; t < 2; t++) {
                uint32_t pa[2][4];
#pragma unroll
                for (int i = 0; i < 2; i++) {
                    pa[i][0] = ex2_f16x2(pk_f16x2(s[i][2*t][0],   s[i][2*t][1]));
                    pa[i][1] = ex2_f16x2(pk_f16x2(s[i][2*t][2],   s[i][2*t][3]));
                    pa[i][2] = ex2_f16x2(pk_f16x2(s[i][2*t+1][0], s[i][2*t+1][1]));
                    pa[i][3] = ex2_f16x2(pk_f16x2(s[i][2*t+1][2], s[i][2*t+1][3]));
                    mma_f16(lacc[i][0], lacc[i][1], lacc[i][2], lacc[i][3],
                            pa[i][0], pa[i][1], pa[i][2], pa[i][3], ONESH2, ONESH2);
                }

                int pairbase = (qq * 2 + t) * 8;
#pragma unroll
                for (int no = 0; no < 4; no++) {
                    uint32_t b0 = Vs[(pairbase + j)     * VV32 + no * 8 + g];
                    uint32_t b1 = Vs[(pairbase + j + 4) * VV32 + no * 8 + g];
#pragma unroll
                    for (int i = 0; i < 2; i++)
                        mma_f16(o[i][no][0], o[i][no][1], o[i][no][2], o[i][no][3],
                                pa[i][0], pa[i][1], pa[i][2], pa[i][3], b0, b1);
                }
            }
        }

        if (c < 31) {
            int nb = 1 - buf;
#pragma unroll
            for (int u = 0; u < 4; u++)
                *(uint4*)&smu[SMEM_K_OFF(nb) + krow[u] * KV32 + kq4[u]] = kpre[u];
#pragma unroll
            for (int u = 0; u < 2; u++) {
                uint4 w0, w1;
                w0.x = prmt(ve[u].x, vo[u].x, 0x5410); w0.y = prmt(ve[u].x, vo[u].x, 0x7632);
                w0.z = prmt(ve[u].y, vo[u].y, 0x5410); w0.w = prmt(ve[u].y, vo[u].y, 0x7632);
                w1.x = prmt(ve[u].z, vo[u].z, 0x5410); w1.y = prmt(ve[u].z, vo[u].z, 0x7632);
                w1.z = prmt(ve[u].w, vo[u].w, 0x5410); w1.w = prmt(ve[u].w, vo[u].w, 0x7632);
                *(uint4*)&smu[SMEM_V_OFF(nb) + vpi[u] * VV32 + vqq[u] * 2]     = w0;
                *(uint4*)&smu[SMEM_V_OFF(nb) + vpi[u] * VV32 + vqq[u] * 2 + 4] = w1;
            }
        }
    }

#pragma unroll
    for (int i = 0; i < 2; i++) {
        float inv0 = 1.0f / lacc[i][0];
        float inv1 = 1.0f / lacc[i][2];
        float* op = O + ((size_t)b * NQ + q0 + wid * 32 + i * 16) * DD + h * DH;
#pragma unroll
        for (int no = 0; no < 4; no++) {
            int col = no * 8 + 2 * j;
            float2 lo = make_float2(o[i][no][0] * inv0, o[i][no][1] * inv0);
            float2 hi = make_float2(o[i][no][2] * inv1, o[i][no][3] * inv1);
            *(float2*)&op[(size_t)g * DD + col]       = lo;
            *(float2*)&op[(size_t)(g + 8) * DD + col] = hi;
        }
    }
}

// =====================================================================
// Launch
// =====================================================================
extern "C" void kernel_launch(void* const* d_in, const int* in_sizes, int n_in,
                              void* d_out, int out_size)
{
    const float* cur_pts = (const float*)d_in[0];
    const float* cur_f   = (const float*)d_in[1];
    const float* nbr_pts = (const float*)d_in[2];
    const float* nbr_f   = (const float*)d_in[3];
    const float* in_w    = (const float*)d_in[4];
    const float* in_b    = (const float*)d_in[5];
    const float* out_w   = (const float*)d_in[6];
    const float* out_b   = (const float*)d_in[7];
    const float* sw      = (const float*)d_in[8];
    const float* sb      = (const float*)d_in[9];
    float* out = (float*)d_out;

    uint32_t *dq, *dk, *dv;
    float *dce, *dan, *dat;
    cudaGetSymbolAddress((void**)&dq,  g_q);
    cudaGetSymbolAddress((void**)&dk,  g_k);
    cudaGetSymbolAddress((void**)&dv,  g_v);
    cudaGetSymbolAddress((void**)&dce, g_cur_edge);
    cudaGetSymbolAddress((void**)&dan, g_all_nbr);
    cudaGetSymbolAddress((void**)&dat, g_attn);

    int flash_smem = FLASH_SMEM_U32 * (int)sizeof(uint32_t);
    int proj_smem  = PROJ_SMEM_FLOATS * (int)sizeof(float);
    static int attr_set = 0;
    if (!attr_set) {
        cudaFuncSetAttribute(flash_mma_kernel,
                             cudaFuncAttributeMaxDynamicSharedMemorySize, flash_smem);
        cudaFuncSetAttribute(gemm_proj_mma,
                             cudaFuncAttributeMaxDynamicSharedMemorySize, proj_smem);
        attr_set = 1;
    }

    // scale folded into Q so P = 2^S in flash: (1/sqrt(32)) * log2(e)
    const float QSCALE = 0.25503488f;

    knn_edge_kernel<<<dim3(NQ / 128, NSETS), 128>>>(cur_pts, nbr_pts, cur_f, nbr_f);

    gemm_proj_mma<<<dim3((BB * NQ) / 128, 4), 256, proj_smem>>>(
        dce, in_w,           in_b,       (float*)dq, 1, QSCALE, nullptr, nullptr, nullptr);
    gemm_proj_mma<<<dim3((BB * LK) / 128, 4), 256, proj_smem>>>(
        dan, in_w + 256*256, in_b + 256, (float*)dk, 1, 1.0f, nullptr, nullptr, nullptr);
    gemm_proj_mma<<<dim3((BB * LK) / 128, 4), 256, proj_smem>>>(
        dan, in_w + 512*256, in_b + 512, (float*)dv, 1, 1.0f, nullptr, nullptr, nullptr);

    flash_mma_kernel<<<dim3(NQ / 128, BB * HH), 128, flash_smem>>>(dq, dk, dv, dat);

    // output projection + fused spatial epilogue (tf32 GEMM, fp32 epilogue)
    gemm_proj_mma<<<dim3((BB * NQ) / 128, 4), 256, proj_smem>>>(
        dat, out_w, out_b, out, 0, 1.0f, cur_pts, sw, sb);
}

// round 14
// speedup vs baseline: 1.1390x; 1.1390x over previous
#include <cuda_runtime.h>
#include <math.h>
#include <stdint.h>

// Problem constants
#define BB   2
#define NQ   2048
#define DD   256
#define HH   8
#define DH   32
#define LK   4096      // M*NN
#define NNK  2048
#define KNN  8
#define NSETS 6

static __device__ __forceinline__ uint32_t f2tf32(float x) {
    uint32_t u;
    asm("cvt.rna.tf32.f32 %0, %1;" : "=r"(u) : "f"(x));
    return u;
}
static __device__ __forceinline__ uint32_t pk_f16x2(float lo, float hi) {
    uint32_t d;
    asm("cvt.rn.f16x2.f32 %0, %1, %2;" : "=r"(d) : "f"(hi), "f"(lo));
    return d;
}
static __device__ __forceinline__ uint32_t ex2_f16x2(uint32_t x) {
    uint32_t d;
    asm("ex2.approx.f16x2 %0, %1;" : "=r"(d) : "r"(x));
    return d;
}
static __device__ __forceinline__ uint32_t prmt(uint32_t a, uint32_t b, uint32_t s) {
    uint32_t d;
    asm("prmt.b32 %0, %1, %2, %3;" : "=r"(d) : "r"(a), "r"(b), "r"(s));
    return d;
}

static __device__ __forceinline__ void mma_tf32(float& d0, float& d1, float& d2, float& d3,
                                                uint32_t a0, uint32_t a1, uint32_t a2, uint32_t a3,
                                                uint32_t b0, uint32_t b1)
{
    asm volatile(
        "mma.sync.aligned.m16n8k8.row.col.f32.tf32.tf32.f32 "
        "{%0,%1,%2,%3}, {%4,%5,%6,%7}, {%8,%9}, {%0,%1,%2,%3};"
        : "+f"(d0), "+f"(d1), "+f"(d2), "+f"(d3)
        : "r"(a0), "r"(a1), "r"(a2), "r"(a3), "r"(b0), "r"(b1));
}

static __device__ __forceinline__ void mma_f16(float& d0, float& d1, float& d2, float& d3,
                                               uint32_t a0, uint32_t a1, uint32_t a2, uint32_t a3,
                                               uint32_t b0, uint32_t b1)
{
    asm volatile(
        "mma.sync.aligned.m16n8k16.row.col.f32.f16.f16.f32 "
        "{%0,%1,%2,%3}, {%4,%5,%6,%7}, {%8,%9}, {%0,%1,%2,%3};"
        : "+f"(d0), "+f"(d1), "+f"(d2), "+f"(d3)
        : "r"(a0), "r"(a1), "r"(a2), "r"(a3), "r"(b0), "r"(b1));
}

#define ONESH2 0x3C003C00u   // f16x2 {1.0, 1.0}

// ---------------- scratch ----------------
__device__ float    g_cur_edge[BB * NQ * DD];
__device__ float    g_all_nbr [BB * LK * DD];
__device__ uint32_t g_q   [BB * NQ * DD / 2];    // f16x2 packed (pre-scaled)
__device__ uint32_t g_k   [BB * LK * DD / 2];
__device__ uint32_t g_v   [BB * LK * DD / 2];
__device__ float    g_attn[BB * NQ * DD];
__device__ int      g_idx [NSETS * NQ * KNN];

// =====================================================================
// Kernel 1: KNN top-8
// =====================================================================
__global__ void knn_topk_kernel(const float* __restrict__ cur_pts,
                                const float* __restrict__ nbr_pts)
{
    int set = blockIdx.y;
    const float* pts = (set < 2) ? (cur_pts + (size_t)set * NQ * 3)
                                 : (nbr_pts + (size_t)(set - 2) * NNK * 3);
    __shared__ float px[2048], py[2048], pz[2048], sq[2048];
    for (int i = threadIdx.x; i < 2048; i += blockDim.x) {
        float x = pts[i * 3 + 0], y = pts[i * 3 + 1], z = pts[i * 3 + 2];
        px[i] = x; py[i] = y; pz[i] = z;
        sq[i] = x * x + y * y + z * z;
    }
    __syncthreads();

    int row = blockIdx.x * blockDim.x + threadIdx.x;
    float bx = px[row], by = py[row], bz = pz[row], bsq = sq[row];

    float bestd[KNN];
    int   besti[KNN];
#pragma unroll
    for (int t = 0; t < KNN; t++) { bestd[t] = INFINITY; besti[t] = -1; }

    for (int j0 = 0; j0 < 2048; j0 += 4) {
        float d2v[4];
#pragma unroll
        for (int u = 0; u < 4; u++) {
            int jj = j0 + u;
            float dot = bx * px[jj] + by * py[jj] + bz * pz[jj];
            d2v[u] = bsq + sq[jj] - 2.0f * dot;
        }
#pragma unroll
        for (int u = 0; u < 4; u++) {
            float d2 = d2v[u];
            if (d2 < bestd[KNN - 1]) {
                int t = KNN - 1;
#pragma unroll
                for (int w = KNN - 1; w > 0; w--) {
                    if (bestd[w - 1] > d2) { bestd[w] = bestd[w - 1]; besti[w] = besti[w - 1]; t = w - 1; }
                    else break;
                }
                bestd[t] = d2; besti[t] = j0 + u;
            }
        }
    }

    int* out = g_idx + ((size_t)set * NQ + row) * KNN;
#pragma unroll
    for (int t = 0; t < KNN; t++) out[t] = besti[t];
}

// =====================================================================
// Kernel 2: edge features (wide grid)
// =====================================================================
__global__ void edge_feats_kernel(const float* __restrict__ cur_f,
                                  const float* __restrict__ nbr_f)
{
    int gid = blockIdx.x;
    int set = gid >> 11;
    int row = gid & 2047;

    const float* f;
    float* outp;
    if (set < 2) {
        f    = cur_f + (size_t)set * NQ * DD;
        outp = g_cur_edge + ((size_t)set * NQ + row) * DD;
    } else {
        int mb = set - 2;
        int m = mb >> 1, b = mb & 1;
        f    = nbr_f + (size_t)mb * NNK * DD;
        outp = g_all_nbr + ((size_t)b * LK + (size_t)m * NNK + row) * DD;
    }

    const int* idx = g_idx + ((size_t)set * NQ + row) * KNN;
    int d = threadIdx.x;

    float acc = 0.0f;
#pragma unroll
    for (int t = 0; t < KNN; t++)
        acc += f[(size_t)idx[t] * DD + d];

    outp[d] = f[(size_t)row * DD + d] - acc * 0.125f;
}

// =====================================================================
// Projection GEMM body (m16n8k8 tf32) — shared by qkv-merged and out-proj
// =====================================================================
#define PSTR 36
#define PROJ_SMEM_FLOATS (2 * 128 * PSTR + 2 * 64 * PSTR)
#define PSM_A(buf) ((buf) * (128 * PSTR))
#define PSM_W(buf) (2 * 128 * PSTR + (buf) * (64 * PSTR))

static __device__ __forceinline__ void
proj_body(float* psm,
          const float* __restrict__ A,
          const float* __restrict__ W,
          const float* __restrict__ bias,
          float* __restrict__ C,
          int out_half, float oscale,
          const float* __restrict__ pts,
          const float* __restrict__ sw,
          const float* __restrict__ sb,
          int m0, int n0)
{
    int tid = threadIdx.x;
    int wid = tid >> 5, lane = tid & 31;
    int g = lane >> 2, j = lane & 3;
    int wm = wid >> 1, wn = wid & 1;

    int ar[4], ac[4];
#pragma unroll
    for (int u = 0; u < 4; u++) {
        int fid = tid + 256 * u;
        ar[u] = fid >> 3;  ac[u] = (fid & 7) * 4;
    }
    int wr[2], wc[2];
#pragma unroll
    for (int u = 0; u < 2; u++) {
        int fid = tid + 256 * u;
        wr[u] = fid >> 3;  wc[u] = (fid & 7) * 4;
    }

    const float* Ab = A + (size_t)m0 * 256;
    const float* Wb = W + (size_t)n0 * 256;

    float acc[2][4][4];
#pragma unroll
    for (int i = 0; i < 2; i++)
#pragma unroll
        for (int n = 0; n < 4; n++)
#pragma unroll
            for (int r = 0; r < 4; r++) acc[i][n][r] = 0.0f;

    float4 apre[4], wpre[2];
#pragma unroll
    for (int u = 0; u < 4; u++) apre[u] = *(const float4*)&Ab[(size_t)ar[u] * 256 + ac[u]];
#pragma unroll
    for (int u = 0; u < 2; u++) wpre[u] = *(const float4*)&Wb[(size_t)wr[u] * 256 + wc[u]];
#pragma unroll
    for (int u = 0; u < 4; u++) {
        uint4 t;
        t.x = f2tf32(apre[u].x); t.y = f2tf32(apre[u].y);
        t.z = f2tf32(apre[u].z); t.w = f2tf32(apre[u].w);
        *(uint4*)&psm[PSM_A(0) + ar[u] * PSTR + ac[u]] = t;
    }
#pragma unroll
    for (int u = 0; u < 2; u++) {
        uint4 t;
        t.x = f2tf32(wpre[u].x); t.y = f2tf32(wpre[u].y);
        t.z = f2tf32(wpre[u].z); t.w = f2tf32(wpre[u].w);
        *(uint4*)&psm[PSM_W(0) + wr[u] * PSTR + wc[u]] = t;
    }

    for (int it = 0; it < 8; it++) {
        int s = it & 1;
        if (it < 7) {
            int ko = (it + 1) * 32;
#pragma unroll
            for (int u = 0; u < 4; u++) apre[u] = *(const float4*)&Ab[(size_t)ar[u] * 256 + ko + ac[u]];
#pragma unroll
            for (int u = 0; u < 2; u++) wpre[u] = *(const float4*)&Wb[(size_t)wr[u] * 256 + ko + wc[u]];
        }
        __syncthreads();
        if (it < 7) {
#pragma unroll
            for (int u = 0; u < 4; u++) {
                uint4 t;
                t.x = f2tf32(apre[u].x); t.y = f2tf32(apre[u].y);
                t.z = f2tf32(apre[u].z); t.w = f2tf32(apre[u].w);
                *(uint4*)&psm[PSM_A(1 - s) + ar[u] * PSTR + ac[u]] = t;
            }
#pragma unroll
            for (int u = 0; u < 2; u++) {
                uint4 t;
                t.x = f2tf32(wpre[u].x); t.y = f2tf32(wpre[u].y);
                t.z = f2tf32(wpre[u].z); t.w = f2tf32(wpre[u].w);
                *(uint4*)&psm[PSM_W(1 - s) + wr[u] * PSTR + wc[u]] = t;
            }
        }

        const uint32_t* As = (const uint32_t*)&psm[PSM_A(s)];
        const uint32_t* Ws = (const uint32_t*)&psm[PSM_W(s)];

#pragma unroll
        for (int kt = 0; kt < 4; kt++) {
            uint32_t af[2][4];
#pragma unroll
            for (int i = 0; i < 2; i++) {
                int rb = wm * 32 + i * 16;
                af[i][0] = As[(rb + g)     * PSTR + kt * 8 + j];
                af[i][1] = As[(rb + g + 8) * PSTR + kt * 8 + j];
                af[i][2] = As[(rb + g)     * PSTR + kt * 8 + j + 4];
                af[i][3] = As[(rb + g + 8) * PSTR + kt * 8 + j + 4];
            }
#pragma unroll
            for (int n = 0; n < 4; n++) {
                int nb = wn * 32 + n * 8;
                uint32_t b0 = Ws[(nb + g) * PSTR + kt * 8 + j];
                uint32_t b1 = Ws[(nb + g) * PSTR + kt * 8 + j + 4];
#pragma unroll
                for (int i = 0; i < 2; i++)
                    mma_tf32(acc[i][n][0], acc[i][n][1], acc[i][n][2], acc[i][n][3],
                             af[i][0], af[i][1], af[i][2], af[i][3], b0, b1);
            }
        }
    }

#pragma unroll
    for (int i = 0; i < 2; i++) {
        int r_lo = m0 + wm * 32 + i * 16 + g;
        float p0a = 0.f, p1a = 0.f, p2a = 0.f, p0b = 0.f, p1b = 0.f, p2b = 0.f;
        if (pts) {
            p0a = pts[r_lo * 3 + 0]; p1a = pts[r_lo * 3 + 1]; p2a = pts[r_lo * 3 + 2];
            p0b = pts[(r_lo + 8) * 3 + 0]; p1b = pts[(r_lo + 8) * 3 + 1]; p2b = pts[(r_lo + 8) * 3 + 2];
        }
#pragma unroll
        for (int n = 0; n < 4; n++) {
            int col = n0 + wn * 32 + n * 8 + 2 * j;
            float b0 = bias[col], b1 = bias[col + 1];
            float v00 = acc[i][n][0] + b0, v01 = acc[i][n][1] + b1;
            float v10 = acc[i][n][2] + b0, v11 = acc[i][n][3] + b1;
            if (pts) {
                float s0 = sw[col * 3], s1 = sw[col * 3 + 1], s2 = sw[col * 3 + 2];
                float t0 = sw[(col+1) * 3], t1 = sw[(col+1) * 3 + 1], t2 = sw[(col+1) * 3 + 2];
                v00 += p0a * s0 + p1a * s1 + p2a * s2 + sb[col];
                v01 += p0a * t0 + p1a * t1 + p2a * t2 + sb[col + 1];
                v10 += p0b * s0 + p1b * s1 + p2b * s2 + sb[col];
                v11 += p0b * t0 + p1b * t1 + p2b * t2 + sb[col + 1];
            }
            if (out_half) {
                uint32_t* Cu = (uint32_t*)C;
                Cu[(size_t)r_lo * 128 + (col >> 1)]       = pk_f16x2(v00 * oscale, v01 * oscale);
                Cu[(size_t)(r_lo + 8) * 128 + (col >> 1)] = pk_f16x2(v10 * oscale, v11 * oscale);
            } else {
                *(float2*)&C[(size_t)r_lo * 256 + col]       = make_float2(v00, v01);
                *(float2*)&C[(size_t)(r_lo + 8) * 256 + col] = make_float2(v10, v11);
            }
        }
    }
}

// ---- merged Q/K/V projection: one launch, 640 blocks ----
// Q rows = BB*NQ = 4096 -> 32 m-blocks x 4 n = 128 blocks
// K rows = BB*LK = 8192 -> 64 x 4 = 256 blocks; V same.
// blocks [0,128): Q ; [128,384): K ; [384,640): V
__global__ void __launch_bounds__(256, 2)
gemm_qkv_mma(const float* __restrict__ Aq,     // cur_edge
             const float* __restrict__ Akv,    // all_nbr
             const float* __restrict__ in_w,
             const float* __restrict__ in_b,
             uint32_t* __restrict__ Cq,
             uint32_t* __restrict__ Ck,
             uint32_t* __restrict__ Cv,
             float qscale)
{
    extern __shared__ float psm[];
    int id = blockIdx.x;
    const float* A; const float* W; const float* bias;
    float* C; float os;
    int t;
    if (id < 128) {
        t = id;       A = Aq;  W = in_w;             bias = in_b;       C = (float*)Cq; os = qscale;
    } else if (id < 384) {
        t = id - 128; A = Akv; W = in_w + 256*256;   bias = in_b + 256; C = (float*)Ck; os = 1.0f;
    } else {
        t = id - 384; A = Akv; W = in_w + 512*256;   bias = in_b + 512; C = (float*)Cv; os = 1.0f;
    }
    int m0 = (t >> 2) * 128;
    int n0 = (t & 3) * 64;
    proj_body(psm, A, W, bias, C, 1, os, nullptr, nullptr, nullptr, m0, n0);
}

// ---- output projection + fused spatial epilogue ----
__global__ void __launch_bounds__(256, 2)
gemm_out_mma(const float* __restrict__ A,
             const float* __restrict__ W,
             const float* __restrict__ bias,
             float* __restrict__ C,
             const float* __restrict__ pts,
             const float* __restrict__ sw,
             const float* __restrict__ sb)
{
    extern __shared__ float psm[];
    proj_body(psm, A, W, bias, C, 0, 1.0f, pts, sw, sb,
              blockIdx.x * 128, blockIdx.y * 64);
}

// =====================================================================
// Kernel 4: flash attention — round-10 config (best known), unchanged
// =====================================================================
#define KV32 20
#define VV32 40
#define SMEM_K_OFF(buf) ((buf) * (128 * KV32))
#define SMEM_V_OFF(buf) (2 * 128 * KV32 + (buf) * (64 * VV32))
#define FLASH_SMEM_U32 (2 * 128 * KV32 + 2 * 64 * VV32)

__global__ void __launch_bounds__(128, 3)
flash_mma_kernel(const uint32_t* __restrict__ Q, const uint32_t* __restrict__ K,
                 const uint32_t* __restrict__ V, float* __restrict__ O)
{
    extern __shared__ uint32_t smu[];

    int tid = threadIdx.x;
    int wid = tid >> 5, lane = tid & 31;
    int g = lane >> 2, j = lane & 3;
    int q0 = blockIdx.x * 128;
    int bh = blockIdx.y, b = bh >> 3, h = bh & 7;

    const uint32_t* qp = Q + ((size_t)b * NQ + q0 + wid * 32) * 128 + h * 16;
    const uint32_t* kp = K + (size_t)b * LK * 128 + h * 16;
    const uint32_t* vp = V + (size_t)b * LK * 128 + h * 16;

    uint32_t aq[2][2][4];
#pragma unroll
    for (int i = 0; i < 2; i++)
#pragma unroll
        for (int kt = 0; kt < 2; kt++) {
            int rb = i * 16;
            aq[i][kt][0] = qp[(size_t)(rb + g) * 128 + kt * 8 + j];
            aq[i][kt][1] = qp[(size_t)(rb + g + 8) * 128 + kt * 8 + j];
            aq[i][kt][2] = qp[(size_t)(rb + g) * 128 + kt * 8 + j + 4];
            aq[i][kt][3] = qp[(size_t)(rb + g + 8) * 128 + kt * 8 + j + 4];
        }

    float o[2][4][4];
#pragma unroll
    for (int i = 0; i < 2; i++)
#pragma unroll
        for (int n = 0; n < 4; n++)
#pragma unroll
            for (int r = 0; r < 4; r++) o[i][n][r] = 0.0f;
    float lacc[2][4] = {{0,0,0,0},{0,0,0,0}};

    int krow[4], kq4[4];
#pragma unroll
    for (int u = 0; u < 4; u++) {
        int fid = tid + 128 * u;
        krow[u] = fid >> 2;
        kq4[u]  = (fid & 3) * 4;
    }
    int vpi[2], vqq[2];
#pragma unroll
    for (int u = 0; u < 2; u++) {
        int fid = tid + 128 * u;
        vpi[u] = fid >> 2;
        vqq[u] = (fid & 3) * 4;
    }

    uint4 kpre[4], ve[2], vo[2];
#pragma unroll
    for (int u = 0; u < 4; u++)
        kpre[u] = *(const uint4*)&kp[(size_t)krow[u] * 128 + kq4[u]];
#pragma unroll
    for (int u = 0; u < 2; u++) {
        ve[u] = *(const uint4*)&vp[(size_t)(2 * vpi[u]) * 128 + vqq[u]];
        vo[u] = *(const uint4*)&vp[(size_t)(2 * vpi[u] + 1) * 128 + vqq[u]];
    }
#pragma unroll
    for (int u = 0; u < 4; u++)
        *(uint4*)&smu[SMEM_K_OFF(0) + krow[u] * KV32 + kq4[u]] = kpre[u];
#pragma unroll
    for (int u = 0; u < 2; u++) {
        uint4 w0, w1;
        w0.x = prmt(ve[u].x, vo[u].x, 0x5410); w0.y = prmt(ve[u].x, vo[u].x, 0x7632);
        w0.z = prmt(ve[u].y, vo[u].y, 0x5410); w0.w = prmt(ve[u].y, vo[u].y, 0x7632);
        w1.x = prmt(ve[u].z, vo[u].z, 0x5410); w1.y = prmt(ve[u].z, vo[u].z, 0x7632);
        w1.z = prmt(ve[u].w, vo[u].w, 0x5410); w1.w = prmt(ve[u].w, vo[u].w, 0x7632);
        *(uint4*)&smu[SMEM_V_OFF(0) + vpi[u] * VV32 + vqq[u] * 2]     = w0;
        *(uint4*)&smu[SMEM_V_OFF(0) + vpi[u] * VV32 + vqq[u] * 2 + 4] = w1;
    }

    for (int c = 0; c < 32; c++) {
        int buf = c & 1;
        if (c < 31) {
            int kb = (c + 1) * 128;
#pragma unroll
            for (int u = 0; u < 4; u++)
                kpre[u] = *(const uint4*)&kp[(size_t)(kb + krow[u]) * 128 + kq4[u]];
#pragma unroll
            for (int u = 0; u < 2; u++) {
                ve[u] = *(const uint4*)&vp[(size_t)(kb + 2 * vpi[u]) * 128 + vqq[u]];
                vo[u] = *(const uint4*)&vp[(size_t)(kb + 2 * vpi[u] + 1) * 128 + vqq[u]];
            }
        }
        __syncthreads();

        const uint32_t* Ks = &smu[SMEM_K_OFF(buf)];
        const uint32_t* Vs = &smu[SMEM_V_OFF(buf)];

#pragma unroll
        for (int qq = 0; qq < 4; qq++) {
            float s[2][4][4];
#pragma unroll
            for (int i = 0; i < 2; i++)
#pragma unroll
                for (int nt = 0; nt < 4; nt++)
#pragma unroll
                    for (int r = 0; r < 4; r++) s[i][nt][r] = 0.0f;

#pragma unroll
            for (int kt = 0; kt < 2; kt++) {
#pragma unroll
                for (int nt = 0; nt < 4; nt++) {
                    int kvrow = qq * 32 + nt * 8 + g;
                    uint32_t b0 = Ks[kvrow * KV32 + kt * 8 + j];
                    uint32_t b1 = Ks[kvrow * KV32 + kt * 8 + j + 4];
#pragma unroll
                    for (int i = 0; i < 2; i++)
                        mma_f16(s[i][nt][0], s[i][nt][1], s[i][nt][2], s[i][nt][3],
                                aq[i][kt][0], aq[i][kt][1], aq[i][kt][2], aq[i][kt][3],
                                b0, b1);
                }
            }

#pragma unroll
            for (int t = 0; t < 2; t++) {
                uint32_t pa[2][4];
#pragma unroll
                for (int i = 0; i < 2; i++) {
                    pa[i][0] = ex2_f16x2(pk_f16x2(s[i][2*t][0],   s[i][2*t][1]));
                    pa[i][1] = ex2_f16x2(pk_f16x2(s[i][2*t][2],   s[i][2*t][3]));
                    pa[i][2] = ex2_f16x2(pk_f16x2(s[i][2*t+1][0], s[i][2*t+1][1]));
                    pa[i][3] = ex2_f16x2(pk_f16x2(s[i][2*t+1][2], s[i][2*t+1][3]));
                    mma_f16(lacc[i][0], lacc[i][1], lacc[i][2], lacc[i][3],
                            pa[i][0], pa[i][1], pa[i][2], pa[i][3], ONESH2, ONESH2);
                }

                int pairbase = (qq * 2 + t) * 8;
#pragma unroll
                for (int no = 0; no < 4; no++) {
                    uint32_t b0 = Vs[(pairbase + j)     * VV32 + no * 8 + g];
                    uint32_t b1 = Vs[(pairbase + j + 4) * VV32 + no * 8 + g];
#pragma unroll
                    for (int i = 0; i < 2; i++)
                        mma_f16(o[i][no][0], o[i][no][1], o[i][no][2], o[i][no][3],
                                pa[i][0], pa[i][1], pa[i][2], pa[i][3], b0, b1);
                }
            }
        }

        if (c < 31) {
            int nb = 1 - buf;
#pragma unroll
            for (int u = 0; u < 4; u++)
                *(uint4*)&smu[SMEM_K_OFF(nb) + krow[u] * KV32 + kq4[u]] = kpre[u];
#pragma unroll
            for (int u = 0; u < 2; u++) {
                uint4 w0, w1;
                w0.x = prmt(ve[u].x, vo[u].x, 0x5410); w0.y = prmt(ve[u].x, vo[u].x, 0x7632);
                w0.z = prmt(ve[u].y, vo[u].y, 0x5410); w0.w = prmt(ve[u].y, vo[u].y, 0x7632);
                w1.x = prmt(ve[u].z, vo[u].z, 0x5410); w1.y = prmt(ve[u].z, vo[u].z, 0x7632);
                w1.z = prmt(ve[u].w, vo[u].w, 0x5410); w1.w = prmt(ve[u].w, vo[u].w, 0x7632);
                *(uint4*)&smu[SMEM_V_OFF(nb) + vpi[u] * VV32 + vqq[u] * 2]     = w0;
                *(uint4*)&smu[SMEM_V_OFF(nb) + vpi[u] * VV32 + vqq[u] * 2 + 4] = w1;
            }
        }
    }

#pragma unroll
    for (int i = 0; i < 2; i++) {
        float inv0 = 1.0f / lacc[i][0];
        float inv1 = 1.0f / lacc[i][2];
        float* op = O + ((size_t)b * NQ + q0 + wid * 32 + i * 16) * DD + h * DH;
#pragma unroll
        for (int no = 0; no < 4; no++) {
            int col = no * 8 + 2 * j;
            float2 lo = make_float2(o[i][no][0] * inv0, o[i][no][1] * inv0);
            float2 hi = make_float2(o[i][no][2] * inv1, o[i][no][3] * inv1);
            *(float2*)&op[(size_t)g * DD + col]       = lo;
            *(float2*)&op[(size_t)(g + 8) * DD + col] = hi;
        }
    }
}

// =====================================================================
// Launch
// =====================================================================
extern "C" void kernel_launch(void* const* d_in, const int* in_sizes, int n_in,
                              void* d_out, int out_size)
{
    const float* cur_pts = (const float*)d_in[0];
    const float* cur_f   = (const float*)d_in[1];
    const float* nbr_pts = (const float*)d_in[2];
    const float* nbr_f   = (const float*)d_in[3];
    const float* in_w    = (const float*)d_in[4];
    const float* in_b    = (const float*)d_in[5];
    const float* out_w   = (const float*)d_in[6];
    const float* out_b   = (const float*)d_in[7];
    const float* sw      = (const float*)d_in[8];
    const float* sb      = (const float*)d_in[9];
    float* out = (float*)d_out;

    uint32_t *dq, *dk, *dv;
    float *dce, *dan, *dat;
    cudaGetSymbolAddress((void**)&dq,  g_q);
    cudaGetSymbolAddress((void**)&dk,  g_k);
    cudaGetSymbolAddress((void**)&dv,  g_v);
    cudaGetSymbolAddress((void**)&dce, g_cur_edge);
    cudaGetSymbolAddress((void**)&dan, g_all_nbr);
    cudaGetSymbolAddress((void**)&dat, g_attn);

    int flash_smem = FLASH_SMEM_U32 * (int)sizeof(uint32_t);
    int proj_smem  = PROJ_SMEM_FLOATS * (int)sizeof(float);
    static int attr_set = 0;
    if (!attr_set) {
        cudaFuncSetAttribute(flash_mma_kernel,
                             cudaFuncAttributeMaxDynamicSharedMemorySize, flash_smem);
        cudaFuncSetAttribute(gemm_qkv_mma,
                             cudaFuncAttributeMaxDynamicSharedMemorySize, proj_smem);
        cudaFuncSetAttribute(gemm_out_mma,
                             cudaFuncAttributeMaxDynamicSharedMemorySize, proj_smem);
        attr_set = 1;
    }

    // scale folded into Q so P = 2^S in flash: (1/sqrt(32)) * log2(e)
    const float QSCALE = 0.25503488f;

    knn_topk_kernel<<<dim3(NQ / 128, NSETS), 128>>>(cur_pts, nbr_pts);
    edge_feats_kernel<<<NSETS * NQ, DD>>>(cur_f, nbr_f);

    // merged Q/K/V projection: one launch, 640 blocks (Q=128, K=256, V=256)
    gemm_qkv_mma<<<640, 256, proj_smem>>>(dce, dan, in_w, in_b, dq, dk, dv, QSCALE);

    flash_mma_kernel<<<dim3(NQ / 128, BB * HH), 128, flash_smem>>>(dq, dk, dv, dat);

    // output projection + fused spatial epilogue (tf32 GEMM, fp32 epilogue)
    gemm_out_mma<<<dim3((BB * NQ) / 128, 4), 256, proj_smem>>>(
        dat, out_w, out_b, out, cur_pts, sw, sb);
}

// round 15
// speedup vs baseline: 1.2915x; 1.1339x over previous
#include <cuda_runtime.h>
#include <math.h>
#include <stdint.h>

// Problem constants
#define BB   2
#define NQ   2048
#define DD   256
#define HH   8
#define DH   32
#define LK   4096      // M*NN
#define NNK  2048
#define KNN  8
#define NSETS 6

static __device__ __forceinline__ uint32_t f2tf32(float x) {
    uint32_t u;
    asm("cvt.rna.tf32.f32 %0, %1;" : "=r"(u) : "f"(x));
    return u;
}
static __device__ __forceinline__ uint32_t pk_f16x2(float lo, float hi) {
    uint32_t d;
    asm("cvt.rn.f16x2.f32 %0, %1, %2;" : "=r"(d) : "f"(hi), "f"(lo));
    return d;
}
static __device__ __forceinline__ uint32_t ex2_f16x2(uint32_t x) {
    uint32_t d;
    asm("ex2.approx.f16x2 %0, %1;" : "=r"(d) : "r"(x));
    return d;
}
static __device__ __forceinline__ uint32_t prmt(uint32_t a, uint32_t b, uint32_t s) {
    uint32_t d;
    asm("prmt.b32 %0, %1, %2, %3;" : "=r"(d) : "r"(a), "r"(b), "r"(s));
    return d;
}

static __device__ __forceinline__ void mma_tf32(float& d0, float& d1, float& d2, float& d3,
                                                uint32_t a0, uint32_t a1, uint32_t a2, uint32_t a3,
                                                uint32_t b0, uint32_t b1)
{
    asm volatile(
        "mma.sync.aligned.m16n8k8.row.col.f32.tf32.tf32.f32 "
        "{%0,%1,%2,%3}, {%4,%5,%6,%7}, {%8,%9}, {%0,%1,%2,%3};"
        : "+f"(d0), "+f"(d1), "+f"(d2), "+f"(d3)
        : "r"(a0), "r"(a1), "r"(a2), "r"(a3), "r"(b0), "r"(b1));
}

static __device__ __forceinline__ void mma_f16(float& d0, float& d1, float& d2, float& d3,
                                               uint32_t a0, uint32_t a1, uint32_t a2, uint32_t a3,
                                               uint32_t b0, uint32_t b1)
{
    asm volatile(
        "mma.sync.aligned.m16n8k16.row.col.f32.f16.f16.f32 "
        "{%0,%1,%2,%3}, {%4,%5,%6,%7}, {%8,%9}, {%0,%1,%2,%3};"
        : "+f"(d0), "+f"(d1), "+f"(d2), "+f"(d3)
        : "r"(a0), "r"(a1), "r"(a2), "r"(a3), "r"(b0), "r"(b1));
}

#define ONESH2 0x3C003C00u   // f16x2 {1.0, 1.0}

// ---------------- scratch ----------------
__device__ float    g_cur_edge[BB * NQ * DD];
__device__ float    g_all_nbr [BB * LK * DD];
__device__ uint32_t g_q   [BB * NQ * DD / 2];    // f16x2 packed (pre-scaled)
__device__ uint32_t g_k   [BB * LK * DD / 2];
__device__ uint32_t g_v   [BB * LK * DD / 2];
__device__ float    g_attn[BB * NQ * DD];
__device__ int      g_idx [NSETS * NQ * KNN];

// =====================================================================
// Kernel 1: KNN top-8 — 64 rows/block, j-range split between 2 threads
// per row, smem merge. grid (32, 6), block 128.
// =====================================================================
__global__ void knn_topk_kernel(const float* __restrict__ cur_pts,
                                const float* __restrict__ nbr_pts)
{
    int set = blockIdx.y;
    const float* pts = (set < 2) ? (cur_pts + (size_t)set * NQ * 3)
                                 : (nbr_pts + (size_t)(set - 2) * NNK * 3);
    __shared__ float px[2048], py[2048], pz[2048], sq[2048];
    __shared__ float smd[128][KNN];
    __shared__ int   smi[128][KNN];

    int tid = threadIdx.x;
    for (int i = tid; i < 2048; i += blockDim.x) {
        float x = pts[i * 3 + 0], y = pts[i * 3 + 1], z = pts[i * 3 + 2];
        px[i] = x; py[i] = y; pz[i] = z;
        sq[i] = x * x + y * y + z * z;
    }
    __syncthreads();

    int rloc = tid & 63;
    int half = tid >> 6;                  // j-range half
    int row = blockIdx.x * 64 + rloc;
    float bx = px[row], by = py[row], bz = pz[row], bsq = sq[row];

    float bestd[KNN];
    int   besti[KNN];
#pragma unroll
    for (int t = 0; t < KNN; t++) { bestd[t] = INFINITY; besti[t] = 0x7fffffff; }

    int jbase = half * 1024;
    for (int j0 = jbase; j0 < jbase + 1024; j0 += 4) {
        float d2v[4];
#pragma unroll
        for (int u = 0; u < 4; u++) {
            int jj = j0 + u;
            float dot = bx * px[jj] + by * py[jj] + bz * pz[jj];
            d2v[u] = bsq + sq[jj] - 2.0f * dot;
        }
#pragma unroll
        for (int u = 0; u < 4; u++) {
            float d2 = d2v[u];
            if (d2 < bestd[KNN - 1]) {
                int t = KNN - 1;
#pragma unroll
                for (int w = KNN - 1; w > 0; w--) {
                    if (bestd[w - 1] > d2) { bestd[w] = bestd[w - 1]; besti[w] = besti[w - 1]; t = w - 1; }
                    else break;
                }
                bestd[t] = d2; besti[t] = j0 + u;
            }
        }
    }

#pragma unroll
    for (int t = 0; t < KNN; t++) { smd[tid][t] = bestd[t]; smi[tid][t] = besti[t]; }
    __syncthreads();

    if (tid < 64) {
        int a = 0, bq = 0;
        int* out = g_idx + ((size_t)set * NQ + blockIdx.x * 64 + tid) * KNN;
#pragma unroll
        for (int t = 0; t < KNN; t++) {
            bool pick_a;
            if (bq >= KNN) pick_a = true;
            else if (a >= KNN) pick_a = false;
            else {
                float da = smd[tid][a], db = smd[tid + 64][bq];
                int   ia = smi[tid][a], ib = smi[tid + 64][bq];
                pick_a = (da < db) || (da == db && ia < ib);
            }
            out[t] = pick_a ? smi[tid][a++] : smi[tid + 64][bq++];
        }
    }
}

// =====================================================================
// Kernel 2: edge features (wide grid)
// =====================================================================
__global__ void edge_feats_kernel(const float* __restrict__ cur_f,
                                  const float* __restrict__ nbr_f)
{
    int gid = blockIdx.x;
    int set = gid >> 11;
    int row = gid & 2047;

    const float* f;
    float* outp;
    if (set < 2) {
        f    = cur_f + (size_t)set * NQ * DD;
        outp = g_cur_edge + ((size_t)set * NQ + row) * DD;
    } else {
        int mb = set - 2;
        int m = mb >> 1, b = mb & 1;
        f    = nbr_f + (size_t)mb * NNK * DD;
        outp = g_all_nbr + ((size_t)b * LK + (size_t)m * NNK + row) * DD;
    }

    const int* idx = g_idx + ((size_t)set * NQ + row) * KNN;
    int d = threadIdx.x;

    float acc = 0.0f;
#pragma unroll
    for (int t = 0; t < KNN; t++)
        acc += f[(size_t)idx[t] * DD + d];

    outp[d] = f[(size_t)row * DD + d] - acc * 0.125f;
}

// =====================================================================
// Projection GEMM body (m16n8k8 tf32) — shared by qkv-merged and out-proj
// =====================================================================
#define PSTR 36
#define PROJ_SMEM_FLOATS (2 * 128 * PSTR + 2 * 64 * PSTR)
#define PSM_A(buf) ((buf) * (128 * PSTR))
#define PSM_W(buf) (2 * 128 * PSTR + (buf) * (64 * PSTR))

static __device__ __forceinline__ void
proj_body(float* psm,
          const float* __restrict__ A,
          const float* __restrict__ W,
          const float* __restrict__ bias,
          float* __restrict__ C,
          int out_half, float oscale,
          const float* __restrict__ pts,
          const float* __restrict__ sw,
          const float* __restrict__ sb,
          int m0, int n0)
{
    int tid = threadIdx.x;
    int wid = tid >> 5, lane = tid & 31;
    int g = lane >> 2, j = lane & 3;
    int wm = wid >> 1, wn = wid & 1;

    int ar[4], ac[4];
#pragma unroll
    for (int u = 0; u < 4; u++) {
        int fid = tid + 256 * u;
        ar[u] = fid >> 3;  ac[u] = (fid & 7) * 4;
    }
    int wr[2], wc[2];
#pragma unroll
    for (int u = 0; u < 2; u++) {
        int fid = tid + 256 * u;
        wr[u] = fid >> 3;  wc[u] = (fid & 7) * 4;
    }

    const float* Ab = A + (size_t)m0 * 256;
    const float* Wb = W + (size_t)n0 * 256;

    float acc[2][4][4];
#pragma unroll
    for (int i = 0; i < 2; i++)
#pragma unroll
        for (int n = 0; n < 4; n++)
#pragma unroll
            for (int r = 0; r < 4; r++) acc[i][n][r] = 0.0f;

    float4 apre[4], wpre[2];
#pragma unroll
    for (int u = 0; u < 4; u++) apre[u] = *(const float4*)&Ab[(size_t)ar[u] * 256 + ac[u]];
#pragma unroll
    for (int u = 0; u < 2; u++) wpre[u] = *(const float4*)&Wb[(size_t)wr[u] * 256 + wc[u]];
#pragma unroll
    for (int u = 0; u < 4; u++) {
        uint4 t;
        t.x = f2tf32(apre[u].x); t.y = f2tf32(apre[u].y);
        t.z = f2tf32(apre[u].z); t.w = f2tf32(apre[u].w);
        *(uint4*)&psm[PSM_A(0) + ar[u] * PSTR + ac[u]] = t;
    }
#pragma unroll
    for (int u = 0; u < 2; u++) {
        uint4 t;
        t.x = f2tf32(wpre[u].x); t.y = f2tf32(wpre[u].y);
        t.z = f2tf32(wpre[u].z); t.w = f2tf32(wpre[u].w);
        *(uint4*)&psm[PSM_W(0) + wr[u] * PSTR + wc[u]] = t;
    }

    for (int it = 0; it < 8; it++) {
        int s = it & 1;
        if (it < 7) {
            int ko = (it + 1) * 32;
#pragma unroll
            for (int u = 0; u < 4; u++) apre[u] = *(const float4*)&Ab[(size_t)ar[u] * 256 + ko + ac[u]];
#pragma unroll
            for (int u = 0; u < 2; u++) wpre[u] = *(const float4*)&Wb[(size_t)wr[u] * 256 + ko + wc[u]];
        }
        __syncthreads();
        if (it < 7) {
#pragma unroll
            for (int u = 0; u < 4; u++) {
                uint4 t;
                t.x = f2tf32(apre[u].x); t.y = f2tf32(apre[u].y);
                t.z = f2tf32(apre[u].z); t.w = f2tf32(apre[u].w);
                *(uint4*)&psm[PSM_A(1 - s) + ar[u] * PSTR + ac[u]] = t;
            }
#pragma unroll
            for (int u = 0; u < 2; u++) {
                uint4 t;
                t.x = f2tf32(wpre[u].x); t.y = f2tf32(wpre[u].y);
                t.z = f2tf32(wpre[u].z); t.w = f2tf32(wpre[u].w);
                *(uint4*)&psm[PSM_W(1 - s) + wr[u] * PSTR + wc[u]] = t;
            }
        }

        const uint32_t* As = (const uint32_t*)&psm[PSM_A(s)];
        const uint32_t* Ws = (const uint32_t*)&psm[PSM_W(s)];

#pragma unroll
        for (int kt = 0; kt < 4; kt++) {
            uint32_t af[2][4];
#pragma unroll
            for (int i = 0; i < 2; i++) {
                int rb = wm * 32 + i * 16;
                af[i][0] = As[(rb + g)     * PSTR + kt * 8 + j];
                af[i][1] = As[(rb + g + 8) * PSTR + kt * 8 + j];
                af[i][2] = As[(rb + g)     * PSTR + kt * 8 + j + 4];
                af[i][3] = As[(rb + g + 8) * PSTR + kt * 8 + j + 4];
            }
#pragma unroll
            for (int n = 0; n < 4; n++) {
                int nb = wn * 32 + n * 8;
                uint32_t b0 = Ws[(nb + g) * PSTR + kt * 8 + j];
                uint32_t b1 = Ws[(nb + g) * PSTR + kt * 8 + j + 4];
#pragma unroll
                for (int i = 0; i < 2; i++)
                    mma_tf32(acc[i][n][0], acc[i][n][1], acc[i][n][2], acc[i][n][3],
                             af[i][0], af[i][1], af[i][2], af[i][3], b0, b1);
            }
        }
    }

#pragma unroll
    for (int i = 0; i < 2; i++) {
        int r_lo = m0 + wm * 32 + i * 16 + g;
        float p0a = 0.f, p1a = 0.f, p2a = 0.f, p0b = 0.f, p1b = 0.f, p2b = 0.f;
        if (pts) {
            p0a = pts[r_lo * 3 + 0]; p1a = pts[r_lo * 3 + 1]; p2a = pts[r_lo * 3 + 2];
            p0b = pts[(r_lo + 8) * 3 + 0]; p1b = pts[(r_lo + 8) * 3 + 1]; p2b = pts[(r_lo + 8) * 3 + 2];
        }
#pragma unroll
        for (int n = 0; n < 4; n++) {
            int col = n0 + wn * 32 + n * 8 + 2 * j;
            float b0 = bias[col], b1 = bias[col + 1];
            float v00 = acc[i][n][0] + b0, v01 = acc[i][n][1] + b1;
            float v10 = acc[i][n][2] + b0, v11 = acc[i][n][3] + b1;
            if (pts) {
                float s0 = sw[col * 3], s1 = sw[col * 3 + 1], s2 = sw[col * 3 + 2];
                float t0 = sw[(col+1) * 3], t1 = sw[(col+1) * 3 + 1], t2 = sw[(col+1) * 3 + 2];
                v00 += p0a * s0 + p1a * s1 + p2a * s2 + sb[col];
                v01 += p0a * t0 + p1a * t1 + p2a * t2 + sb[col + 1];
                v10 += p0b * s0 + p1b * s1 + p2b * s2 + sb[col];
                v11 += p0b * t0 + p1b * t1 + p2b * t2 + sb[col + 1];
            }
            if (out_half) {
                uint32_t* Cu = (uint32_t*)C;
                Cu[(size_t)r_lo * 128 + (col >> 1)]       = pk_f16x2(v00 * oscale, v01 * oscale);
                Cu[(size_t)(r_lo + 8) * 128 + (col >> 1)] = pk_f16x2(v10 * oscale, v11 * oscale);
            } else {
                *(float2*)&C[(size_t)r_lo * 256 + col]       = make_float2(v00, v01);
                *(float2*)&C[(size_t)(r_lo + 8) * 256 + col] = make_float2(v10, v11);
            }
        }
    }
}

// ---- merged Q/K/V projection: one launch, 640 blocks ----
__global__ void __launch_bounds__(256, 2)
gemm_qkv_mma(const float* __restrict__ Aq,
             const float* __restrict__ Akv,
             const float* __restrict__ in_w,
             const float* __restrict__ in_b,
             uint32_t* __restrict__ Cq,
             uint32_t* __restrict__ Ck,
             uint32_t* __restrict__ Cv,
             float qscale)
{
    extern __shared__ float psm[];
    int id = blockIdx.x;
    const float* A; const float* W; const float* bias;
    float* C; float os;
    int t;
    if (id < 128) {
        t = id;       A = Aq;  W = in_w;             bias = in_b;       C = (float*)Cq; os = qscale;
    } else if (id < 384) {
        t = id - 128; A = Akv; W = in_w + 256*256;   bias = in_b + 256; C = (float*)Ck; os = 1.0f;
    } else {
        t = id - 384; A = Akv; W = in_w + 512*256;   bias = in_b + 512; C = (float*)Cv; os = 1.0f;
    }
    int m0 = (t >> 2) * 128;
    int n0 = (t & 3) * 64;
    proj_body(psm, A, W, bias, C, 1, os, nullptr, nullptr, nullptr, m0, n0);
}

// ---- output projection + fused spatial epilogue ----
__global__ void __launch_bounds__(256, 2)
gemm_out_mma(const float* __restrict__ A,
             const float* __restrict__ W,
             const float* __restrict__ bias,
             float* __restrict__ C,
             const float* __restrict__ pts,
             const float* __restrict__ sw,
             const float* __restrict__ sb)
{
    extern __shared__ float psm[];
    proj_body(psm, A, W, bias, C, 0, 1.0f, pts, sw, sb,
              blockIdx.x * 128, blockIdx.y * 64);
}

// =====================================================================
// Kernel 4: flash attention — 256 threads / 8 warps: two warp-groups
// split the kv columns of each chunk (wg=wid>>2 owns cols [wg*64,+64)),
// same staging traffic as 4-warp version; partial O/l combined via smem.
// q-tile 128 (w4 = wid&3 owns 32 q-rows). occ 1, ~8 warps/SM, short chains.
// =====================================================================
#define KV32 20
#define VV32 40
#define SMEM_K_OFF(buf) ((buf) * (128 * KV32))
#define SMEM_V_OFF(buf) (2 * 128 * KV32 + (buf) * (64 * VV32))
#define FLASH_SMEM_U32 (2 * 128 * KV32 + 2 * 64 * VV32)

__global__ void __launch_bounds__(256, 1)
flash_mma_kernel(const uint32_t* __restrict__ Q, const uint32_t* __restrict__ K,
                 const uint32_t* __restrict__ V, float* __restrict__ O)
{
    extern __shared__ uint32_t smu[];

    int tid = threadIdx.x;
    int wid = tid >> 5, lane = tid & 31;
    int g = lane >> 2, j = lane & 3;
    int wg = wid >> 2, w4 = wid & 3;
    int q0 = blockIdx.x * 128;
    int bh = blockIdx.y, b = bh >> 3, h = bh & 7;

    const uint32_t* qp = Q + ((size_t)b * NQ + q0 + w4 * 32) * 128 + h * 16;
    const uint32_t* kp = K + (size_t)b * LK * 128 + h * 16;
    const uint32_t* vp = V + (size_t)b * LK * 128 + h * 16;

    uint32_t aq[2][2][4];
#pragma unroll
    for (int i = 0; i < 2; i++)
#pragma unroll
        for (int kt = 0; kt < 2; kt++) {
            int rb = i * 16;
            aq[i][kt][0] = qp[(size_t)(rb + g) * 128 + kt * 8 + j];
            aq[i][kt][1] = qp[(size_t)(rb + g + 8) * 128 + kt * 8 + j];
            aq[i][kt][2] = qp[(size_t)(rb + g) * 128 + kt * 8 + j + 4];
            aq[i][kt][3] = qp[(size_t)(rb + g + 8) * 128 + kt * 8 + j + 4];
        }

    float o[2][4][4];
#pragma unroll
    for (int i = 0; i < 2; i++)
#pragma unroll
        for (int n = 0; n < 4; n++)
#pragma unroll
            for (int r = 0; r < 4; r++) o[i][n][r] = 0.0f;
    float lacc[2][4] = {{0,0,0,0},{0,0,0,0}};

    // staging maps (256 threads): K 512 uint4 (2/thr), V 256 slots (1/thr)
    int krow[2], kq4[2];
#pragma unroll
    for (int u = 0; u < 2; u++) {
        int fid = tid + 256 * u;
        krow[u] = fid >> 2;
        kq4[u]  = (fid & 3) * 4;
    }
    int vpi = tid >> 2, vqq = (tid & 3) * 4;

    uint4 kpre[2], ve, vo;
#pragma unroll
    for (int u = 0; u < 2; u++)
        kpre[u] = *(const uint4*)&kp[(size_t)krow[u] * 128 + kq4[u]];
    ve = *(const uint4*)&vp[(size_t)(2 * vpi) * 128 + vqq];
    vo = *(const uint4*)&vp[(size_t)(2 * vpi + 1) * 128 + vqq];

#pragma unroll
    for (int u = 0; u < 2; u++)
        *(uint4*)&smu[SMEM_K_OFF(0) + krow[u] * KV32 + kq4[u]] = kpre[u];
    {
        uint4 w0, w1;
        w0.x = prmt(ve.x, vo.x, 0x5410); w0.y = prmt(ve.x, vo.x, 0x7632);
        w0.z = prmt(ve.y, vo.y, 0x5410); w0.w = prmt(ve.y, vo.y, 0x7632);
        w1.x = prmt(ve.z, vo.z, 0x5410); w1.y = prmt(ve.z, vo.z, 0x7632);
        w1.z = prmt(ve.w, vo.w, 0x5410); w1.w = prmt(ve.w, vo.w, 0x7632);
        *(uint4*)&smu[SMEM_V_OFF(0) + vpi * VV32 + vqq * 2]     = w0;
        *(uint4*)&smu[SMEM_V_OFF(0) + vpi * VV32 + vqq * 2 + 4] = w1;
    }

    for (int c = 0; c < 32; c++) {
        int buf = c & 1;
        if (c < 31) {
            int kb = (c + 1) * 128;
#pragma unroll
            for (int u = 0; u < 2; u++)
                kpre[u] = *(const uint4*)&kp[(size_t)(kb + krow[u]) * 128 + kq4[u]];
            ve = *(const uint4*)&vp[(size_t)(kb + 2 * vpi) * 128 + vqq];
            vo = *(const uint4*)&vp[(size_t)(kb + 2 * vpi + 1) * 128 + vqq];
        }
        __syncthreads();

        const uint32_t* Ks = &smu[SMEM_K_OFF(buf)];
        const uint32_t* Vs = &smu[SMEM_V_OFF(buf)];

        // this warp's kv half: columns [wg*64, wg*64+64), two quarters of 32
#pragma unroll
        for (int qq = 0; qq < 2; qq++) {
            float s[2][4][4];
#pragma unroll
            for (int i = 0; i < 2; i++)
#pragma unroll
                for (int nt = 0; nt < 4; nt++)
#pragma unroll
                    for (int r = 0; r < 4; r++) s[i][nt][r] = 0.0f;

#pragma unroll
            for (int kt = 0; kt < 2; kt++) {
#pragma unroll
                for (int nt = 0; nt < 4; nt++) {
                    int kvrow = wg * 64 + qq * 32 + nt * 8 + g;
                    uint32_t b0 = Ks[kvrow * KV32 + kt * 8 + j];
                    uint32_t b1 = Ks[kvrow * KV32 + kt * 8 + j + 4];
#pragma unroll
                    for (int i = 0; i < 2; i++)
                        mma_f16(s[i][nt][0], s[i][nt][1], s[i][nt][2], s[i][nt][3],
                                aq[i][kt][0], aq[i][kt][1], aq[i][kt][2], aq[i][kt][3],
                                b0, b1);
                }
            }

#pragma unroll
            for (int t = 0; t < 2; t++) {
                uint32_t pa[2][4];
#pragma unroll
                for (int i = 0; i < 2; i++) {
                    pa[i][0] = ex2_f16x2(pk_f16x2(s[i][2*t][0],   s[i][2*t][1]));
                    pa[i][1] = ex2_f16x2(pk_f16x2(s[i][2*t][2],   s[i][2*t][3]));
                    pa[i][2] = ex2_f16x2(pk_f16x2(s[i][2*t+1][0], s[i][2*t+1][1]));
                    pa[i][3] = ex2_f16x2(pk_f16x2(s[i][2*t+1][2], s[i][2*t+1][3]));
                    mma_f16(lacc[i][0], lacc[i][1], lacc[i][2], lacc[i][3],
                            pa[i][0], pa[i][1], pa[i][2], pa[i][3], ONESH2, ONESH2);
                }

                int pairbase = wg * 32 + (qq * 2 + t) * 8;
#pragma unroll
                for (int no = 0; no < 4; no++) {
                    uint32_t b0 = Vs[(pairbase + j)     * VV32 + no * 8 + g];
                    uint32_t b1 = Vs[(pairbase + j + 4) * VV32 + no * 8 + g];
#pragma unroll
                    for (int i = 0; i < 2; i++)
                        mma_f16(o[i][no][0], o[i][no][1], o[i][no][2], o[i][no][3],
                                pa[i][0], pa[i][1], pa[i][2], pa[i][3], b0, b1);
                }
            }
        }

        if (c < 31) {
            int nb = 1 - buf;
#pragma unroll
            for (int u = 0; u < 2; u++)
                *(uint4*)&smu[SMEM_K_OFF(nb) + krow[u] * KV32 + kq4[u]] = kpre[u];
            uint4 w0, w1;
            w0.x = prmt(ve.x, vo.x, 0x5410); w0.y = prmt(ve.x, vo.x, 0x7632);
            w0.z = prmt(ve.y, vo.y, 0x5410); w0.w = prmt(ve.y, vo.y, 0x7632);
            w1.x = prmt(ve.z, vo.z, 0x5410); w1.y = prmt(ve.z, vo.z, 0x7632);
            w1.z = prmt(ve.w, vo.w, 0x5410); w1.w = prmt(ve.w, vo.w, 0x7632);
            *(uint4*)&smu[SMEM_V_OFF(nb) + vpi * VV32 + vqq * 2]     = w0;
            *(uint4*)&smu[SMEM_V_OFF(nb) + vpi * VV32 + vqq * 2 + 4] = w1;
        }
    }

    // ---- combine the two kv-half partials via smem (reuse staging) ----
    __syncthreads();                       // all compute done; smem reusable
    float* osm = (float*)smu;
    int slot = (tid & 127) * 36;
    if (wg == 1) {
#pragma unroll
        for (int i = 0; i < 2; i++)
#pragma unroll
            for (int no = 0; no < 4; no++)
#pragma unroll
                for (int r = 0; r < 4; r++)
                    osm[slot + (i * 4 + no) * 4 + r] = o[i][no][r];
        osm[slot + 32] = lacc[0][0];
        osm[slot + 33] = lacc[0][2];
        osm[slot + 34] = lacc[1][0];
        osm[slot + 35] = lacc[1][2];
    }
    __syncthreads();
    if (wg == 0) {
#pragma unroll
        for (int i = 0; i < 2; i++) {
            float l0 = lacc[i][0] + osm[slot + 32 + i * 2];
            float l1 = lacc[i][2] + osm[slot + 33 + i * 2];
            float inv0 = 1.0f / l0, inv1 = 1.0f / l1;
            float* op = O + ((size_t)b * NQ + q0 + w4 * 32 + i * 16) * DD + h * DH;
#pragma unroll
            for (int no = 0; no < 4; no++) {
                int col = no * 8 + 2 * j;
                float v0 = o[i][no][0] + osm[slot + (i * 4 + no) * 4 + 0];
                float v1 = o[i][no][1] + osm[slot + (i * 4 + no) * 4 + 1];
                float v2 = o[i][no][2] + osm[slot + (i * 4 + no) * 4 + 2];
                float v3 = o[i][no][3] + osm[slot + (i * 4 + no) * 4 + 3];
                *(float2*)&op[(size_t)g * DD + col]       = make_float2(v0 * inv0, v1 * inv0);
                *(float2*)&op[(size_t)(g + 8) * DD + col] = make_float2(v2 * inv1, v3 * inv1);
            }
        }
    }
}

// =====================================================================
// Launch
// =====================================================================
extern "C" void kernel_launch(void* const* d_in, const int* in_sizes, int n_in,
                              void* d_out, int out_size)
{
    const float* cur_pts = (const float*)d_in[0];
    const float* cur_f   = (const float*)d_in[1];
    const float* nbr_pts = (const float*)d_in[2];
    const float* nbr_f   = (const float*)d_in[3];
    const float* in_w    = (const float*)d_in[4];
    const float* in_b    = (const float*)d_in[5];
    const float* out_w   = (const float*)d_in[6];
    const float* out_b   = (const float*)d_in[7];
    const float* sw      = (const float*)d_in[8];
    const float* sb      = (const float*)d_in[9];
    float* out = (float*)d_out;

    uint32_t *dq, *dk, *dv;
    float *dce, *dan, *dat;
    cudaGetSymbolAddress((void**)&dq,  g_q);
    cudaGetSymbolAddress((void**)&dk,  g_k);
    cudaGetSymbolAddress((void**)&dv,  g_v);
    cudaGetSymbolAddress((void**)&dce, g_cur_edge);
    cudaGetSymbolAddress((void**)&dan, g_all_nbr);
    cudaGetSymbolAddress((void**)&dat, g_attn);

    int flash_smem = FLASH_SMEM_U32 * (int)sizeof(uint32_t);
    int proj_smem  = PROJ_SMEM_FLOATS * (int)sizeof(float);
    static int attr_set = 0;
    if (!attr_set) {
        cudaFuncSetAttribute(flash_mma_kernel,
                             cudaFuncAttributeMaxDynamicSharedMemorySize, flash_smem);
        cudaFuncSetAttribute(gemm_qkv_mma,
                             cudaFuncAttributeMaxDynamicSharedMemorySize, proj_smem);
        cudaFuncSetAttribute(gemm_out_mma,
                             cudaFuncAttributeMaxDynamicSharedMemorySize, proj_smem);
        attr_set = 1;
    }

    // scale folded into Q so P = 2^S in flash: (1/sqrt(32)) * log2(e)
    const float QSCALE = 0.25503488f;

    knn_topk_kernel<<<dim3(NQ / 64, NSETS), 128>>>(cur_pts, nbr_pts);
    edge_feats_kernel<<<NSETS * NQ, DD>>>(cur_f, nbr_f);

    gemm_qkv_mma<<<640, 256, proj_smem>>>(dce, dan, in_w, in_b, dq, dk, dv, QSCALE);

    flash_mma_kernel<<<dim3(NQ / 128, BB * HH), 256, flash_smem>>>(dq, dk, dv, dat);

    gemm_out_mma<<<dim3((BB * NQ) / 128, 4), 256, proj_smem>>>(
        dat, out_w, out_b, out, cur_pts, sw, sb);
}

// round 16
// speedup vs baseline: 1.3585x; 1.0519x over previous
#include <cuda_runtime.h>
#include <math.h>
#include <stdint.h>

// Problem constants
#define BB   2
#define NQ   2048
#define DD   256
#define HH   8
#define DH   32
#define LK   4096      // M*NN
#define NNK  2048
#define KNN  8
#define NSETS 6

static __device__ __forceinline__ uint32_t f2tf32(float x) {
    uint32_t u;
    asm("cvt.rna.tf32.f32 %0, %1;" : "=r"(u) : "f"(x));
    return u;
}
static __device__ __forceinline__ uint32_t pk_f16x2(float lo, float hi) {
    uint32_t d;
    asm("cvt.rn.f16x2.f32 %0, %1, %2;" : "=r"(d) : "f"(hi), "f"(lo));
    return d;
}
static __device__ __forceinline__ uint32_t ex2_f16x2(uint32_t x) {
    uint32_t d;
    asm("ex2.approx.f16x2 %0, %1;" : "=r"(d) : "r"(x));
    return d;
}
static __device__ __forceinline__ uint32_t prmt(uint32_t a, uint32_t b, uint32_t s) {
    uint32_t d;
    asm("prmt.b32 %0, %1, %2, %3;" : "=r"(d) : "r"(a), "r"(b), "r"(s));
    return d;
}

static __device__ __forceinline__ void mma_tf32(float& d0, float& d1, float& d2, float& d3,
                                                uint32_t a0, uint32_t a1, uint32_t a2, uint32_t a3,
                                                uint32_t b0, uint32_t b1)
{
    asm volatile(
        "mma.sync.aligned.m16n8k8.row.col.f32.tf32.tf32.f32 "
        "{%0,%1,%2,%3}, {%4,%5,%6,%7}, {%8,%9}, {%0,%1,%2,%3};"
        : "+f"(d0), "+f"(d1), "+f"(d2), "+f"(d3)
        : "r"(a0), "r"(a1), "r"(a2), "r"(a3), "r"(b0), "r"(b1));
}

static __device__ __forceinline__ void mma_f16(float& d0, float& d1, float& d2, float& d3,
                                               uint32_t a0, uint32_t a1, uint32_t a2, uint32_t a3,
                                               uint32_t b0, uint32_t b1)
{
    asm volatile(
        "mma.sync.aligned.m16n8k16.row.col.f32.f16.f16.f32 "
        "{%0,%1,%2,%3}, {%4,%5,%6,%7}, {%8,%9}, {%0,%1,%2,%3};"
        : "+f"(d0), "+f"(d1), "+f"(d2), "+f"(d3)
        : "r"(a0), "r"(a1), "r"(a2), "r"(a3), "r"(b0), "r"(b1));
}

#define ONESH2 0x3C003C00u   // f16x2 {1.0, 1.0}

// ---------------- scratch ----------------
__device__ uint32_t g_cur_edge[BB * NQ * DD / 2];   // f16x2 packed
__device__ uint32_t g_all_nbr [BB * LK * DD / 2];   // f16x2 packed
__device__ uint32_t g_q   [BB * NQ * DD / 2];       // f16x2 packed (pre-scaled)
__device__ uint32_t g_k   [BB * LK * DD / 2];
__device__ uint32_t g_v   [BB * LK * DD / 2];
__device__ float    g_attn[BB * NQ * DD];
__device__ int      g_idx [NSETS * NQ * KNN];

// =====================================================================
// Kernel 1: KNN top-8 — 64 rows/block, split-j, smem merge (validated)
// =====================================================================
__global__ void knn_topk_kernel(const float* __restrict__ cur_pts,
                                const float* __restrict__ nbr_pts)
{
    int set = blockIdx.y;
    const float* pts = (set < 2) ? (cur_pts + (size_t)set * NQ * 3)
                                 : (nbr_pts + (size_t)(set - 2) * NNK * 3);
    __shared__ float px[2048], py[2048], pz[2048], sq[2048];
    __shared__ float smd[128][KNN];
    __shared__ int   smi[128][KNN];

    int tid = threadIdx.x;
    for (int i = tid; i < 2048; i += blockDim.x) {
        float x = pts[i * 3 + 0], y = pts[i * 3 + 1], z = pts[i * 3 + 2];
        px[i] = x; py[i] = y; pz[i] = z;
        sq[i] = x * x + y * y + z * z;
    }
    __syncthreads();

    int rloc = tid & 63;
    int half = tid >> 6;
    int row = blockIdx.x * 64 + rloc;
    float bx = px[row], by = py[row], bz = pz[row], bsq = sq[row];

    float bestd[KNN];
    int   besti[KNN];
#pragma unroll
    for (int t = 0; t < KNN; t++) { bestd[t] = INFINITY; besti[t] = 0x7fffffff; }

    int jbase = half * 1024;
    for (int j0 = jbase; j0 < jbase + 1024; j0 += 4) {
        float d2v[4];
#pragma unroll
        for (int u = 0; u < 4; u++) {
            int jj = j0 + u;
            float dot = bx * px[jj] + by * py[jj] + bz * pz[jj];
            d2v[u] = bsq + sq[jj] - 2.0f * dot;
        }
#pragma unroll
        for (int u = 0; u < 4; u++) {
            float d2 = d2v[u];
            if (d2 < bestd[KNN - 1]) {
                int t = KNN - 1;
#pragma unroll
                for (int w = KNN - 1; w > 0; w--) {
                    if (bestd[w - 1] > d2) { bestd[w] = bestd[w - 1]; besti[w] = besti[w - 1]; t = w - 1; }
                    else break;
                }
                bestd[t] = d2; besti[t] = j0 + u;
            }
        }
    }

#pragma unroll
    for (int t = 0; t < KNN; t++) { smd[tid][t] = bestd[t]; smi[tid][t] = besti[t]; }
    __syncthreads();

    if (tid < 64) {
        int a = 0, bq = 0;
        int* out = g_idx + ((size_t)set * NQ + blockIdx.x * 64 + tid) * KNN;
#pragma unroll
        for (int t = 0; t < KNN; t++) {
            bool pick_a;
            if (bq >= KNN) pick_a = true;
            else if (a >= KNN) pick_a = false;
            else {
                float da = smd[tid][a], db = smd[tid + 64][bq];
                int   ia = smi[tid][a], ib = smi[tid + 64][bq];
                pick_a = (da < db) || (da == db && ia < ib);
            }
            out[t] = pick_a ? smi[tid][a++] : smi[tid + 64][bq++];
        }
    }
}

// =====================================================================
// Kernel 2: edge features — emits packed f16x2 (halved traffic)
// block 128: thread = d-pair
// =====================================================================
__global__ void edge_feats_kernel(const float* __restrict__ cur_f,
                                  const float* __restrict__ nbr_f)
{
    int gid = blockIdx.x;
    int set = gid >> 11;
    int row = gid & 2047;

    const float* f;
    uint32_t* outp;
    if (set < 2) {
        f    = cur_f + (size_t)set * NQ * DD;
        outp = g_cur_edge + ((size_t)set * NQ + row) * 128;
    } else {
        int mb = set - 2;
        int m = mb >> 1, b = mb & 1;
        f    = nbr_f + (size_t)mb * NNK * DD;
        outp = g_all_nbr + ((size_t)b * LK + (size_t)m * NNK + row) * 128;
    }

    const int* idx = g_idx + ((size_t)set * NQ + row) * KNN;
    int d2 = threadIdx.x;          // pair 0..127

    float ax = 0.0f, ay = 0.0f;
#pragma unroll
    for (int t = 0; t < KNN; t++) {
        float2 v = *(const float2*)&f[(size_t)idx[t] * DD + d2 * 2];
        ax += v.x; ay += v.y;
    }
    float2 s = *(const float2*)&f[(size_t)row * DD + d2 * 2];
    outp[d2] = pk_f16x2(s.x - ax * 0.125f, s.y - ay * 0.125f);
}

// =====================================================================
// Kernel 3a: merged Q/K/V projection — f16 m16n8k16 MMA
// A pre-packed f16x2 (edge output); W converted to f16 at staging.
// CTA tile 128x64, 8 warps (4m x 2n), k-chunk 32 (16 u32), double-buffered.
// smem strides 20 u32 (conflict-free frag loads, flash-validated pattern).
// =====================================================================
#define HSTR 20
#define QKV_SMEM_U32 (2 * 128 * HSTR + 2 * 64 * HSTR)
#define HSM_A(buf) ((buf) * (128 * HSTR))
#define HSM_W(buf) (2 * 128 * HSTR + (buf) * (64 * HSTR))

__global__ void __launch_bounds__(256, 2)
gemm_qkv_mma(const uint32_t* __restrict__ Aq,
             const uint32_t* __restrict__ Akv,
             const float* __restrict__ in_w,
             const float* __restrict__ in_b,
             uint32_t* __restrict__ Cq,
             uint32_t* __restrict__ Ck,
             uint32_t* __restrict__ Cv,
             float qscale)
{
    extern __shared__ uint32_t hsm[];

    int id = blockIdx.x;
    const uint32_t* A; const float* W; const float* bias;
    uint32_t* C; float os;
    int t;
    if (id < 128) {
        t = id;       A = Aq;  W = in_w;             bias = in_b;       C = Cq; os = qscale;
    } else if (id < 384) {
        t = id - 128; A = Akv; W = in_w + 256*256;   bias = in_b + 256; C = Ck; os = 1.0f;
    } else {
        t = id - 384; A = Akv; W = in_w + 512*256;   bias = in_b + 512; C = Cv; os = 1.0f;
    }
    int m0 = (t >> 2) * 128;
    int n0 = (t & 3) * 64;

    int tid = threadIdx.x;
    int wid = tid >> 5, lane = tid & 31;
    int g = lane >> 2, j = lane & 3;
    int wm = wid >> 1, wn = wid & 1;

    // staging maps: A chunk 128 rows x 16 u32 -> 512 uint4, 2/thr
    int ar[2], ac[2];
#pragma unroll
    for (int u = 0; u < 2; u++) {
        int fid = tid + 256 * u;
        ar[u] = fid >> 2;  ac[u] = (fid & 3) * 4;   // u32 quad within 16
    }
    // W chunk 64 rows x 32 f32 -> 512 float4, 2/thr; each packs to uint2
    int wr[2], wc[2];
#pragma unroll
    for (int u = 0; u < 2; u++) {
        int fid = tid + 256 * u;
        wr[u] = fid >> 3;  wc[u] = (fid & 7) * 4;   // f32 quad within 32
    }

    const uint32_t* Ab = A + (size_t)m0 * 128;
    const float*    Wb = W + (size_t)n0 * 256;

    float acc[2][4][4];
#pragma unroll
    for (int i = 0; i < 2; i++)
#pragma unroll
        for (int n = 0; n < 4; n++)
#pragma unroll
            for (int r = 0; r < 4; r++) acc[i][n][r] = 0.0f;

    uint4  apre[2];
    float4 wpre[2];
#pragma unroll
    for (int u = 0; u < 2; u++) {
        apre[u] = *(const uint4*)&Ab[(size_t)ar[u] * 128 + ac[u]];
        wpre[u] = *(const float4*)&Wb[(size_t)wr[u] * 256 + wc[u]];
    }
#pragma unroll
    for (int u = 0; u < 2; u++) {
        *(uint4*)&hsm[HSM_A(0) + ar[u] * HSTR + ac[u]] = apre[u];
        uint2 wp;
        wp.x = pk_f16x2(wpre[u].x, wpre[u].y);
        wp.y = pk_f16x2(wpre[u].z, wpre[u].w);
        *(uint2*)&hsm[HSM_W(0) + wr[u] * HSTR + (wc[u] >> 1)] = wp;
    }

    for (int it = 0; it < 8; it++) {
        int s = it & 1;
        if (it < 7) {
            int ko32 = (it + 1) * 16;     // u32 offset in A row
            int kof  = (it + 1) * 32;     // f32 offset in W row
#pragma unroll
            for (int u = 0; u < 2; u++) {
                apre[u] = *(const uint4*)&Ab[(size_t)ar[u] * 128 + ko32 + ac[u]];
                wpre[u] = *(const float4*)&Wb[(size_t)wr[u] * 256 + kof + wc[u]];
            }
        }
        __syncthreads();
        if (it < 7) {
#pragma unroll
            for (int u = 0; u < 2; u++) {
                *(uint4*)&hsm[HSM_A(1 - s) + ar[u] * HSTR + ac[u]] = apre[u];
                uint2 wp;
                wp.x = pk_f16x2(wpre[u].x, wpre[u].y);
                wp.y = pk_f16x2(wpre[u].z, wpre[u].w);
                *(uint2*)&hsm[HSM_W(1 - s) + wr[u] * HSTR + (wc[u] >> 1)] = wp;
            }
        }

        const uint32_t* As = &hsm[HSM_A(s)];
        const uint32_t* Ws = &hsm[HSM_W(s)];

#pragma unroll
        for (int kt = 0; kt < 2; kt++) {
            uint32_t af[2][4];
#pragma unroll
            for (int i = 0; i < 2; i++) {
                int rb = wm * 32 + i * 16;
                af[i][0] = As[(rb + g)     * HSTR + kt * 8 + j];
                af[i][1] = As[(rb + g + 8) * HSTR + kt * 8 + j];
                af[i][2] = As[(rb + g)     * HSTR + kt * 8 + j + 4];
                af[i][3] = As[(rb + g + 8) * HSTR + kt * 8 + j + 4];
            }
#pragma unroll
            for (int n = 0; n < 4; n++) {
                int nb = wn * 32 + n * 8;
                uint32_t b0 = Ws[(nb + g) * HSTR + kt * 8 + j];
                uint32_t b1 = Ws[(nb + g) * HSTR + kt * 8 + j + 4];
#pragma unroll
                for (int i = 0; i < 2; i++)
                    mma_f16(acc[i][n][0], acc[i][n][1], acc[i][n][2], acc[i][n][3],
                            af[i][0], af[i][1], af[i][2], af[i][3], b0, b1);
            }
        }
    }

#pragma unroll
    for (int i = 0; i < 2; i++) {
        int r_lo = m0 + wm * 32 + i * 16 + g;
#pragma unroll
        for (int n = 0; n < 4; n++) {
            int col = n0 + wn * 32 + n * 8 + 2 * j;
            float b0 = bias[col], b1 = bias[col + 1];
            C[(size_t)r_lo * 128 + (col >> 1)] =
                pk_f16x2((acc[i][n][0] + b0) * os, (acc[i][n][1] + b1) * os);
            C[(size_t)(r_lo + 8) * 128 + (col >> 1)] =
                pk_f16x2((acc[i][n][2] + b0) * os, (acc[i][n][3] + b1) * os);
        }
    }
}

// =====================================================================
// Kernel 3b: output projection (tf32, fp32 A) + fused spatial epilogue
// =====================================================================
#define PSTR 36
#define PROJ_SMEM_FLOATS (2 * 128 * PSTR + 2 * 64 * PSTR)
#define PSM_A(buf) ((buf) * (128 * PSTR))
#define PSM_W(buf) (2 * 128 * PSTR + (buf) * (64 * PSTR))

__global__ void __launch_bounds__(256, 2)
gemm_out_mma(const float* __restrict__ A,
             const float* __restrict__ W,
             const float* __restrict__ bias,
             float* __restrict__ C,
             const float* __restrict__ pts,
             const float* __restrict__ sw,
             const float* __restrict__ sb)
{
    extern __shared__ float psm[];
    int m0 = blockIdx.x * 128, n0 = blockIdx.y * 64;

    int tid = threadIdx.x;
    int wid = tid >> 5, lane = tid & 31;
    int g = lane >> 2, j = lane & 3;
    int wm = wid >> 1, wn = wid & 1;

    int ar[4], ac[4];
#pragma unroll
    for (int u = 0; u < 4; u++) {
        int fid = tid + 256 * u;
        ar[u] = fid >> 3;  ac[u] = (fid & 7) * 4;
    }
    int wr[2], wc[2];
#pragma unroll
    for (int u = 0; u < 2; u++) {
        int fid = tid + 256 * u;
        wr[u] = fid >> 3;  wc[u] = (fid & 7) * 4;
    }

    const float* Ab = A + (size_t)m0 * 256;
    const float* Wb = W + (size_t)n0 * 256;

    float acc[2][4][4];
#pragma unroll
    for (int i = 0; i < 2; i++)
#pragma unroll
        for (int n = 0; n < 4; n++)
#pragma unroll
            for (int r = 0; r < 4; r++) acc[i][n][r] = 0.0f;

    float4 apre[4], wpre[2];
#pragma unroll
    for (int u = 0; u < 4; u++) apre[u] = *(const float4*)&Ab[(size_t)ar[u] * 256 + ac[u]];
#pragma unroll
    for (int u = 0; u < 2; u++) wpre[u] = *(const float4*)&Wb[(size_t)wr[u] * 256 + wc[u]];
#pragma unroll
    for (int u = 0; u < 4; u++) {
        uint4 t;
        t.x = f2tf32(apre[u].x); t.y = f2tf32(apre[u].y);
        t.z = f2tf32(apre[u].z); t.w = f2tf32(apre[u].w);
        *(uint4*)&psm[PSM_A(0) + ar[u] * PSTR + ac[u]] = t;
    }
#pragma unroll
    for (int u = 0; u < 2; u++) {
        uint4 t;
        t.x = f2tf32(wpre[u].x); t.y = f2tf32(wpre[u].y);
        t.z = f2tf32(wpre[u].z); t.w = f2tf32(wpre[u].w);
        *(uint4*)&psm[PSM_W(0) + wr[u] * PSTR + wc[u]] = t;
    }

    for (int it = 0; it < 8; it++) {
        int s = it & 1;
        if (it < 7) {
            int ko = (it + 1) * 32;
#pragma unroll
            for (int u = 0; u < 4; u++) apre[u] = *(const float4*)&Ab[(size_t)ar[u] * 256 + ko + ac[u]];
#pragma unroll
            for (int u = 0; u < 2; u++) wpre[u] = *(const float4*)&Wb[(size_t)wr[u] * 256 + ko + wc[u]];
        }
        __syncthreads();
        if (it < 7) {
#pragma unroll
            for (int u = 0; u < 4; u++) {
                uint4 t;
                t.x = f2tf32(apre[u].x); t.y = f2tf32(apre[u].y);
                t.z = f2tf32(apre[u].z); t.w = f2tf32(apre[u].w);
                *(uint4*)&psm[PSM_A(1 - s) + ar[u] * PSTR + ac[u]] = t;
            }
#pragma unroll
            for (int u = 0; u < 2; u++) {
                uint4 t;
                t.x = f2tf32(wpre[u].x); t.y = f2tf32(wpre[u].y);
                t.z = f2tf32(wpre[u].z); t.w = f2tf32(wpre[u].w);
                *(uint4*)&psm[PSM_W(1 - s) + wr[u] * PSTR + wc[u]] = t;
            }
        }

        const uint32_t* As = (const uint32_t*)&psm[PSM_A(s)];
        const uint32_t* Ws = (const uint32_t*)&psm[PSM_W(s)];

#pragma unroll
        for (int kt = 0; kt < 4; kt++) {
            uint32_t af[2][4];
#pragma unroll
            for (int i = 0; i < 2; i++) {
                int rb = wm * 32 + i * 16;
                af[i][0] = As[(rb + g)     * PSTR + kt * 8 + j];
                af[i][1] = As[(rb + g + 8) * PSTR + kt * 8 + j];
                af[i][2] = As[(rb + g)     * PSTR + kt * 8 + j + 4];
                af[i][3] = As[(rb + g + 8) * PSTR + kt * 8 + j + 4];
            }
#pragma unroll
            for (int n = 0; n < 4; n++) {
                int nb = wn * 32 + n * 8;
                uint32_t b0 = Ws[(nb + g) * PSTR + kt * 8 + j];
                uint32_t b1 = Ws[(nb + g) * PSTR + kt * 8 + j + 4];
#pragma unroll
                for (int i = 0; i < 2; i++)
                    mma_tf32(acc[i][n][0], acc[i][n][1], acc[i][n][2], acc[i][n][3],
                             af[i][0], af[i][1], af[i][2], af[i][3], b0, b1);
            }
        }
    }

#pragma unroll
    for (int i = 0; i < 2; i++) {
        int r_lo = m0 + wm * 32 + i * 16 + g;
        float p0a = pts[r_lo * 3 + 0], p1a = pts[r_lo * 3 + 1], p2a = pts[r_lo * 3 + 2];
        float p0b = pts[(r_lo + 8) * 3 + 0], p1b = pts[(r_lo + 8) * 3 + 1], p2b = pts[(r_lo + 8) * 3 + 2];
#pragma unroll
        for (int n = 0; n < 4; n++) {
            int col = n0 + wn * 32 + n * 8 + 2 * j;
            float b0 = bias[col], b1 = bias[col + 1];
            float s0 = sw[col * 3], s1 = sw[col * 3 + 1], s2 = sw[col * 3 + 2];
            float t0 = sw[(col+1) * 3], t1 = sw[(col+1) * 3 + 1], t2 = sw[(col+1) * 3 + 2];
            float v00 = acc[i][n][0] + b0 + p0a * s0 + p1a * s1 + p2a * s2 + sb[col];
            float v01 = acc[i][n][1] + b1 + p0a * t0 + p1a * t1 + p2a * t2 + sb[col + 1];
            float v10 = acc[i][n][2] + b0 + p0b * s0 + p1b * s1 + p2b * s2 + sb[col];
            float v11 = acc[i][n][3] + b1 + p0b * t0 + p1b * t1 + p2b * t2 + sb[col + 1];
            *(float2*)&C[(size_t)r_lo * 256 + col]       = make_float2(v00, v01);
            *(float2*)&C[(size_t)(r_lo + 8) * 256 + col] = make_float2(v10, v11);
        }
    }
}

// =====================================================================
// Kernel 4: flash attention — round-15 config (best known), unchanged
// =====================================================================
#define KV32 20
#define VV32 40
#define SMEM_K_OFF(buf) ((buf) * (128 * KV32))
#define SMEM_V_OFF(buf) (2 * 128 * KV32 + (buf) * (64 * VV32))
#define FLASH_SMEM_U32 (2 * 128 * KV32 + 2 * 64 * VV32)

__global__ void __launch_bounds__(256, 1)
flash_mma_kernel(const uint32_t* __restrict__ Q, const uint32_t* __restrict__ K,
                 const uint32_t* __restrict__ V, float* __restrict__ O)
{
    extern __shared__ uint32_t smu[];

    int tid = threadIdx.x;
    int wid = tid >> 5, lane = tid & 31;
    int g = lane >> 2, j = lane & 3;
    int wg = wid >> 2, w4 = wid & 3;
    int q0 = blockIdx.x * 128;
    int bh = blockIdx.y, b = bh >> 3, h = bh & 7;

    const uint32_t* qp = Q + ((size_t)b * NQ + q0 + w4 * 32) * 128 + h * 16;
    const uint32_t* kp = K + (size_t)b * LK * 128 + h * 16;
    const uint32_t* vp = V + (size_t)b * LK * 128 + h * 16;

    uint32_t aq[2][2][4];
#pragma unroll
    for (int i = 0; i < 2; i++)
#pragma unroll
        for (int kt = 0; kt < 2; kt++) {
            int rb = i * 16;
            aq[i][kt][0] = qp[(size_t)(rb + g) * 128 + kt * 8 + j];
            aq[i][kt][1] = qp[(size_t)(rb + g + 8) * 128 + kt * 8 + j];
            aq[i][kt][2] = qp[(size_t)(rb + g) * 128 + kt * 8 + j + 4];
            aq[i][kt][3] = qp[(size_t)(rb + g + 8) * 128 + kt * 8 + j + 4];
        }

    float o[2][4][4];
#pragma unroll
    for (int i = 0; i < 2; i++)
#pragma unroll
        for (int n = 0; n < 4; n++)
#pragma unroll
            for (int r = 0; r < 4; r++) o[i][n][r] = 0.0f;
    float lacc[2][4] = {{0,0,0,0},{0,0,0,0}};

    int krow[2], kq4[2];
#pragma unroll
    for (int u = 0; u < 2; u++) {
        int fid = tid + 256 * u;
        krow[u] = fid >> 2;
        kq4[u]  = (fid & 3) * 4;
    }
    int vpi = tid >> 2, vqq = (tid & 3) * 4;

    uint4 kpre[2], ve, vo;
#pragma unroll
    for (int u = 0; u < 2; u++)
        kpre[u] = *(const uint4*)&kp[(size_t)krow[u] * 128 + kq4[u]];
    ve = *(const uint4*)&vp[(size_t)(2 * vpi) * 128 + vqq];
    vo = *(const uint4*)&vp[(size_t)(2 * vpi + 1) * 128 + vqq];

#pragma unroll
    for (int u = 0; u < 2; u++)
        *(uint4*)&smu[SMEM_K_OFF(0) + krow[u] * KV32 + kq4[u]] = kpre[u];
    {
        uint4 w0, w1;
        w0.x = prmt(ve.x, vo.x, 0x5410); w0.y = prmt(ve.x, vo.x, 0x7632);
        w0.z = prmt(ve.y, vo.y, 0x5410); w0.w = prmt(ve.y, vo.y, 0x7632);
        w1.x = prmt(ve.z, vo.z, 0x5410); w1.y = prmt(ve.z, vo.z, 0x7632);
        w1.z = prmt(ve.w, vo.w, 0x5410); w1.w = prmt(ve.w, vo.w, 0x7632);
        *(uint4*)&smu[SMEM_V_OFF(0) + vpi * VV32 + vqq * 2]     = w0;
        *(uint4*)&smu[SMEM_V_OFF(0) + vpi * VV32 + vqq * 2 + 4] = w1;
    }

    for (int c = 0; c < 32; c++) {
        int buf = c & 1;
        if (c < 31) {
            int kb = (c + 1) * 128;
#pragma unroll
            for (int u = 0; u < 2; u++)
                kpre[u] = *(const uint4*)&kp[(size_t)(kb + krow[u]) * 128 + kq4[u]];
            ve = *(const uint4*)&vp[(size_t)(kb + 2 * vpi) * 128 + vqq];
            vo = *(const uint4*)&vp[(size_t)(kb + 2 * vpi + 1) * 128 + vqq];
        }
        __syncthreads();

        const uint32_t* Ks = &smu[SMEM_K_OFF(buf)];
        const uint32_t* Vs = &smu[SMEM_V_OFF(buf)];

#pragma unroll
        for (int qq = 0; qq < 2; qq++) {
            float s[2][4][4];
#pragma unroll
            for (int i = 0; i < 2; i++)
#pragma unroll
                for (int nt = 0; nt < 4; nt++)
#pragma unroll
                    for (int r = 0; r < 4; r++) s[i][nt][r] = 0.0f;

#pragma unroll
            for (int kt = 0; kt < 2; kt++) {
#pragma unroll
                for (int nt = 0; nt < 4; nt++) {
                    int kvrow = wg * 64 + qq * 32 + nt * 8 + g;
                    uint32_t b0 = Ks[kvrow * KV32 + kt * 8 + j];
                    uint32_t b1 = Ks[kvrow * KV32 + kt * 8 + j + 4];
#pragma unroll
                    for (int i = 0; i < 2; i++)
                        mma_f16(s[i][nt][0], s[i][nt][1], s[i][nt][2], s[i][nt][3],
                                aq[i][kt][0], aq[i][kt][1], aq[i][kt][2], aq[i][kt][3],
                                b0, b1);
                }
            }

#pragma unroll
            for (int t = 0; t < 2; t++) {
                uint32_t pa[2][4];
#pragma unroll
                for (int i = 0; i < 2; i++) {
                    pa[i][0] = ex2_f16x2(pk_f16x2(s[i][2*t][0],   s[i][2*t][1]));
                    pa[i][1] = ex2_f16x2(pk_f16x2(s[i][2*t][2],   s[i][2*t][3]));
                    pa[i][2] = ex2_f16x2(pk_f16x2(s[i][2*t+1][0], s[i][2*t+1][1]));
                    pa[i][3] = ex2_f16x2(pk_f16x2(s[i][2*t+1][2], s[i][2*t+1][3]));
                    mma_f16(lacc[i][0], lacc[i][1], lacc[i][2], lacc[i][3],
                            pa[i][0], pa[i][1], pa[i][2], pa[i][3], ONESH2, ONESH2);
                }

                int pairbase = wg * 32 + (qq * 2 + t) * 8;
#pragma unroll
                for (int no = 0; no < 4; no++) {
                    uint32_t b0 = Vs[(pairbase + j)     * VV32 + no * 8 + g];
                    uint32_t b1 = Vs[(pairbase + j + 4) * VV32 + no * 8 + g];
#pragma unroll
                    for (int i = 0; i < 2; i++)
                        mma_f16(o[i][no][0], o[i][no][1], o[i][no][2], o[i][no][3],
                                pa[i][0], pa[i][1], pa[i][2], pa[i][3], b0, b1);
                }
            }
        }

        if (c < 31) {
            int nb = 1 - buf;
#pragma unroll
            for (int u = 0; u < 2; u++)
                *(uint4*)&smu[SMEM_K_OFF(nb) + krow[u] * KV32 + kq4[u]] = kpre[u];
            uint4 w0, w1;
            w0.x = prmt(ve.x, vo.x, 0x5410); w0.y = prmt(ve.x, vo.x, 0x7632);
            w0.z = prmt(ve.y, vo.y, 0x5410); w0.w = prmt(ve.y, vo.y, 0x7632);
            w1.x = prmt(ve.z, vo.z, 0x5410); w1.y = prmt(ve.z, vo.z, 0x7632);
            w1.z = prmt(ve.w, vo.w, 0x5410); w1.w = prmt(ve.w, vo.w, 0x7632);
            *(uint4*)&smu[SMEM_V_OFF(nb) + vpi * VV32 + vqq * 2]     = w0;
            *(uint4*)&smu[SMEM_V_OFF(nb) + vpi * VV32 + vqq * 2 + 4] = w1;
        }
    }

    __syncthreads();
    float* osm = (float*)smu;
    int slot = (tid & 127) * 36;
    if (wg == 1) {
#pragma unroll
        for (int i = 0; i < 2; i++)
#pragma unroll
            for (int no = 0; no < 4; no++)
#pragma unroll
                for (int r = 0; r < 4; r++)
                    osm[slot + (i * 4 + no) * 4 + r] = o[i][no][r];
        osm[slot + 32] = lacc[0][0];
        osm[slot + 33] = lacc[0][2];
        osm[slot + 34] = lacc[1][0];
        osm[slot + 35] = lacc[1][2];
    }
    __syncthreads();
    if (wg == 0) {
#pragma unroll
        for (int i = 0; i < 2; i++) {
            float l0 = lacc[i][0] + osm[slot + 32 + i * 2];
            float l1 = lacc[i][2] + osm[slot + 33 + i * 2];
            float inv0 = 1.0f / l0, inv1 = 1.0f / l1;
            float* op = O + ((size_t)b * NQ + q0 + w4 * 32 + i * 16) * DD + h * DH;
#pragma unroll
            for (int no = 0; no < 4; no++) {
                int col = no * 8 + 2 * j;
                float v0 = o[i][no][0] + osm[slot + (i * 4 + no) * 4 + 0];
                float v1 = o[i][no][1] + osm[slot + (i * 4 + no) * 4 + 1];
                float v2 = o[i][no][2] + osm[slot + (i * 4 + no) * 4 + 2];
                float v3 = o[i][no][3] + osm[slot + (i * 4 + no) * 4 + 3];
                *(float2*)&op[(size_t)g * DD + col]       = make_float2(v0 * inv0, v1 * inv0);
                *(float2*)&op[(size_t)(g + 8) * DD + col] = make_float2(v2 * inv1, v3 * inv1);
            }
        }
    }
}

// =====================================================================
// Launch
// =====================================================================
extern "C" void kernel_launch(void* const* d_in, const int* in_sizes, int n_in,
                              void* d_out, int out_size)
{
    const float* cur_pts = (const float*)d_in[0];
    const float* cur_f   = (const float*)d_in[1];
    const float* nbr_pts = (const float*)d_in[2];
    const float* nbr_f   = (const float*)d_in[3];
    const float* in_w    = (const float*)d_in[4];
    const float* in_b    = (const float*)d_in[5];
    const float* out_w   = (const float*)d_in[6];
    const float* out_b   = (const float*)d_in[7];
    const float* sw      = (const float*)d_in[8];
    const float* sb      = (const float*)d_in[9];
    float* out = (float*)d_out;

    uint32_t *dq, *dk, *dv, *dce, *dan;
    float *dat;
    cudaGetSymbolAddress((void**)&dq,  g_q);
    cudaGetSymbolAddress((void**)&dk,  g_k);
    cudaGetSymbolAddress((void**)&dv,  g_v);
    cudaGetSymbolAddress((void**)&dce, g_cur_edge);
    cudaGetSymbolAddress((void**)&dan, g_all_nbr);
    cudaGetSymbolAddress((void**)&dat, g_attn);

    int flash_smem = FLASH_SMEM_U32 * (int)sizeof(uint32_t);
    int qkv_smem   = QKV_SMEM_U32 * (int)sizeof(uint32_t);
    int out_smem   = PROJ_SMEM_FLOATS * (int)sizeof(float);
    static int attr_set = 0;
    if (!attr_set) {
        cudaFuncSetAttribute(flash_mma_kernel,
                             cudaFuncAttributeMaxDynamicSharedMemorySize, flash_smem);
        cudaFuncSetAttribute(gemm_qkv_mma,
                             cudaFuncAttributeMaxDynamicSharedMemorySize, qkv_smem);
        cudaFuncSetAttribute(gemm_out_mma,
                             cudaFuncAttributeMaxDynamicSharedMemorySize, out_smem);
        attr_set = 1;
    }

    // scale folded into Q so P = 2^S in flash: (1/sqrt(32)) * log2(e)
    const float QSCALE = 0.25503488f;

    knn_topk_kernel<<<dim3(NQ / 64, NSETS), 128>>>(cur_pts, nbr_pts);
    edge_feats_kernel<<<NSETS * NQ, 128>>>(cur_f, nbr_f);

    gemm_qkv_mma<<<640, 256, qkv_smem>>>(dce, dan, in_w, in_b, dq, dk, dv, QSCALE);

    flash_mma_kernel<<<dim3(NQ / 128, BB * HH), 256, flash_smem>>>(dq, dk, dv, dat);

    gemm_out_mma<<<dim3((BB * NQ) / 128, 4), 256, out_smem>>>(
        dat, out_w, out_b, out, cur_pts, sw, sb);
}

// round 17
// speedup vs baseline: 1.4022x; 1.0321x over previous
#include <cuda_runtime.h>
#include <math.h>
#include <stdint.h>

// Problem constants
#define BB   2
#define NQ   2048
#define DD   256
#define HH   8
#define DH   32
#define LK   4096      // M*NN
#define NNK  2048
#define KNN  8
#define NSETS 6

static __device__ __forceinline__ uint32_t pk_f16x2(float lo, float hi) {
    uint32_t d;
    asm("cvt.rn.f16x2.f32 %0, %1, %2;" : "=r"(d) : "f"(hi), "f"(lo));
    return d;
}
static __device__ __forceinline__ uint32_t ex2_f16x2(uint32_t x) {
    uint32_t d;
    asm("ex2.approx.f16x2 %0, %1;" : "=r"(d) : "r"(x));
    return d;
}
static __device__ __forceinline__ uint32_t prmt(uint32_t a, uint32_t b, uint32_t s) {
    uint32_t d;
    asm("prmt.b32 %0, %1, %2, %3;" : "=r"(d) : "r"(a), "r"(b), "r"(s));
    return d;
}

static __device__ __forceinline__ void mma_f16(float& d0, float& d1, float& d2, float& d3,
                                               uint32_t a0, uint32_t a1, uint32_t a2, uint32_t a3,
                                               uint32_t b0, uint32_t b1)
{
    asm volatile(
        "mma.sync.aligned.m16n8k16.row.col.f32.f16.f16.f32 "
        "{%0,%1,%2,%3}, {%4,%5,%6,%7}, {%8,%9}, {%0,%1,%2,%3};"
        : "+f"(d0), "+f"(d1), "+f"(d2), "+f"(d3)
        : "r"(a0), "r"(a1), "r"(a2), "r"(a3), "r"(b0), "r"(b1));
}

#define ONESH2 0x3C003C00u   // f16x2 {1.0, 1.0}

// ---------------- scratch ----------------
__device__ uint32_t g_cur_edge[BB * NQ * DD / 2];   // f16x2 packed
__device__ uint32_t g_all_nbr [BB * LK * DD / 2];
__device__ uint32_t g_q   [BB * NQ * DD / 2];       // f16x2 packed (pre-scaled)
__device__ uint32_t g_k   [BB * LK * DD / 2];
__device__ uint32_t g_v   [BB * LK * DD / 2];
__device__ uint32_t g_attn[BB * NQ * DD / 2];       // f16x2 packed attention output
__device__ int      g_idx [NSETS * NQ * KNN];

// =====================================================================
// Kernel 1: KNN top-8 — 64 rows/block, split-j, smem merge (validated)
// =====================================================================
__global__ void knn_topk_kernel(const float* __restrict__ cur_pts,
                                const float* __restrict__ nbr_pts)
{
    int set = blockIdx.y;
    const float* pts = (set < 2) ? (cur_pts + (size_t)set * NQ * 3)
                                 : (nbr_pts + (size_t)(set - 2) * NNK * 3);
    __shared__ float px[2048], py[2048], pz[2048], sq[2048];
    __shared__ float smd[128][KNN];
    __shared__ int   smi[128][KNN];

    int tid = threadIdx.x;
    for (int i = tid; i < 2048; i += blockDim.x) {
        float x = pts[i * 3 + 0], y = pts[i * 3 + 1], z = pts[i * 3 + 2];
        px[i] = x; py[i] = y; pz[i] = z;
        sq[i] = x * x + y * y + z * z;
    }
    __syncthreads();

    int rloc = tid & 63;
    int half = tid >> 6;
    int row = blockIdx.x * 64 + rloc;
    float bx = px[row], by = py[row], bz = pz[row], bsq = sq[row];

    float bestd[KNN];
    int   besti[KNN];
#pragma unroll
    for (int t = 0; t < KNN; t++) { bestd[t] = INFINITY; besti[t] = 0x7fffffff; }

    int jbase = half * 1024;
    for (int j0 = jbase; j0 < jbase + 1024; j0 += 4) {
        float d2v[4];
#pragma unroll
        for (int u = 0; u < 4; u++) {
            int jj = j0 + u;
            float dot = bx * px[jj] + by * py[jj] + bz * pz[jj];
            d2v[u] = bsq + sq[jj] - 2.0f * dot;
        }
#pragma unroll
        for (int u = 0; u < 4; u++) {
            float d2 = d2v[u];
            if (d2 < bestd[KNN - 1]) {
                int t = KNN - 1;
#pragma unroll
                for (int w = KNN - 1; w > 0; w--) {
                    if (bestd[w - 1] > d2) { bestd[w] = bestd[w - 1]; besti[w] = besti[w - 1]; t = w - 1; }
                    else break;
                }
                bestd[t] = d2; besti[t] = j0 + u;
            }
        }
    }

#pragma unroll
    for (int t = 0; t < KNN; t++) { smd[tid][t] = bestd[t]; smi[tid][t] = besti[t]; }
    __syncthreads();

    if (tid < 64) {
        int a = 0, bq = 0;
        int* out = g_idx + ((size_t)set * NQ + blockIdx.x * 64 + tid) * KNN;
#pragma unroll
        for (int t = 0; t < KNN; t++) {
            bool pick_a;
            if (bq >= KNN) pick_a = true;
            else if (a >= KNN) pick_a = false;
            else {
                float da = smd[tid][a], db = smd[tid + 64][bq];
                int   ia = smi[tid][a], ib = smi[tid + 64][bq];
                pick_a = (da < db) || (da == db && ia < ib);
            }
            out[t] = pick_a ? smi[tid][a++] : smi[tid + 64][bq++];
        }
    }
}

// =====================================================================
// Kernel 2: edge features — emits packed f16x2
// =====================================================================
__global__ void edge_feats_kernel(const float* __restrict__ cur_f,
                                  const float* __restrict__ nbr_f)
{
    int gid = blockIdx.x;
    int set = gid >> 11;
    int row = gid & 2047;

    const float* f;
    uint32_t* outp;
    if (set < 2) {
        f    = cur_f + (size_t)set * NQ * DD;
        outp = g_cur_edge + ((size_t)set * NQ + row) * 128;
    } else {
        int mb = set - 2;
        int m = mb >> 1, b = mb & 1;
        f    = nbr_f + (size_t)mb * NNK * DD;
        outp = g_all_nbr + ((size_t)b * LK + (size_t)m * NNK + row) * 128;
    }

    const int* idx = g_idx + ((size_t)set * NQ + row) * KNN;
    int d2 = threadIdx.x;

    float ax = 0.0f, ay = 0.0f;
#pragma unroll
    for (int t = 0; t < KNN; t++) {
        float2 v = *(const float2*)&f[(size_t)idx[t] * DD + d2 * 2];
        ax += v.x; ay += v.y;
    }
    float2 s = *(const float2*)&f[(size_t)row * DD + d2 * 2];
    outp[d2] = pk_f16x2(s.x - ax * 0.125f, s.y - ay * 0.125f);
}

// =====================================================================
// f16 GEMM body (m16n8k16): A pre-packed f16x2, W f32 packed at staging.
// CTA tile 128x64, 8 warps (4m x 2n), k-chunk 32 (16 u32), double-buffered.
// =====================================================================
#define HSTR 20
#define QKV_SMEM_U32 (2 * 128 * HSTR + 2 * 64 * HSTR)
#define HSM_A(buf) ((buf) * (128 * HSTR))
#define HSM_W(buf) (2 * 128 * HSTR + (buf) * (64 * HSTR))

// templated-by-flag epilogue: out_half => packed f16 out; else fp32 + spatial
static __device__ __forceinline__ void
gemm_f16_body(uint32_t* hsm,
              const uint32_t* __restrict__ A,
              const float* __restrict__ W,
              const float* __restrict__ bias,
              void* __restrict__ C,
              int out_half, float oscale,
              const float* __restrict__ pts,
              const float* __restrict__ sw,
              const float* __restrict__ sb,
              int m0, int n0)
{
    int tid = threadIdx.x;
    int wid = tid >> 5, lane = tid & 31;
    int g = lane >> 2, j = lane & 3;
    int wm = wid >> 1, wn = wid & 1;

    int ar[2], ac[2];
#pragma unroll
    for (int u = 0; u < 2; u++) {
        int fid = tid + 256 * u;
        ar[u] = fid >> 2;  ac[u] = (fid & 3) * 4;
    }
    int wr[2], wc[2];
#pragma unroll
    for (int u = 0; u < 2; u++) {
        int fid = tid + 256 * u;
        wr[u] = fid >> 3;  wc[u] = (fid & 7) * 4;
    }

    const uint32_t* Ab = A + (size_t)m0 * 128;
    const float*    Wb = W + (size_t)n0 * 256;

    float acc[2][4][4];
#pragma unroll
    for (int i = 0; i < 2; i++)
#pragma unroll
        for (int n = 0; n < 4; n++)
#pragma unroll
            for (int r = 0; r < 4; r++) acc[i][n][r] = 0.0f;

    uint4  apre[2];
    float4 wpre[2];
#pragma unroll
    for (int u = 0; u < 2; u++) {
        apre[u] = *(const uint4*)&Ab[(size_t)ar[u] * 128 + ac[u]];
        wpre[u] = *(const float4*)&Wb[(size_t)wr[u] * 256 + wc[u]];
    }
#pragma unroll
    for (int u = 0; u < 2; u++) {
        *(uint4*)&hsm[HSM_A(0) + ar[u] * HSTR + ac[u]] = apre[u];
        uint2 wp;
        wp.x = pk_f16x2(wpre[u].x, wpre[u].y);
        wp.y = pk_f16x2(wpre[u].z, wpre[u].w);
        *(uint2*)&hsm[HSM_W(0) + wr[u] * HSTR + (wc[u] >> 1)] = wp;
    }

    for (int it = 0; it < 8; it++) {
        int s = it & 1;
        if (it < 7) {
            int ko32 = (it + 1) * 16;
            int kof  = (it + 1) * 32;
#pragma unroll
            for (int u = 0; u < 2; u++) {
                apre[u] = *(const uint4*)&Ab[(size_t)ar[u] * 128 + ko32 + ac[u]];
                wpre[u] = *(const float4*)&Wb[(size_t)wr[u] * 256 + kof + wc[u]];
            }
        }
        __syncthreads();
        if (it < 7) {
#pragma unroll
            for (int u = 0; u < 2; u++) {
                *(uint4*)&hsm[HSM_A(1 - s) + ar[u] * HSTR + ac[u]] = apre[u];
                uint2 wp;
                wp.x = pk_f16x2(wpre[u].x, wpre[u].y);
                wp.y = pk_f16x2(wpre[u].z, wpre[u].w);
                *(uint2*)&hsm[HSM_W(1 - s) + wr[u] * HSTR + (wc[u] >> 1)] = wp;
            }
        }

        const uint32_t* As = &hsm[HSM_A(s)];
        const uint32_t* Ws = &hsm[HSM_W(s)];

#pragma unroll
        for (int kt = 0; kt < 2; kt++) {
            uint32_t af[2][4];
#pragma unroll
            for (int i = 0; i < 2; i++) {
                int rb = wm * 32 + i * 16;
                af[i][0] = As[(rb + g)     * HSTR + kt * 8 + j];
                af[i][1] = As[(rb + g + 8) * HSTR + kt * 8 + j];
                af[i][2] = As[(rb + g)     * HSTR + kt * 8 + j + 4];
                af[i][3] = As[(rb + g + 8) * HSTR + kt * 8 + j + 4];
            }
#pragma unroll
            for (int n = 0; n < 4; n++) {
                int nb = wn * 32 + n * 8;
                uint32_t b0 = Ws[(nb + g) * HSTR + kt * 8 + j];
                uint32_t b1 = Ws[(nb + g) * HSTR + kt * 8 + j + 4];
#pragma unroll
                for (int i = 0; i < 2; i++)
                    mma_f16(acc[i][n][0], acc[i][n][1], acc[i][n][2], acc[i][n][3],
                            af[i][0], af[i][1], af[i][2], af[i][3], b0, b1);
            }
        }
    }

#pragma unroll
    for (int i = 0; i < 2; i++) {
        int r_lo = m0 + wm * 32 + i * 16 + g;
        float p0a = 0.f, p1a = 0.f, p2a = 0.f, p0b = 0.f, p1b = 0.f, p2b = 0.f;
        if (!out_half) {
            p0a = pts[r_lo * 3 + 0]; p1a = pts[r_lo * 3 + 1]; p2a = pts[r_lo * 3 + 2];
            p0b = pts[(r_lo + 8) * 3 + 0]; p1b = pts[(r_lo + 8) * 3 + 1]; p2b = pts[(r_lo + 8) * 3 + 2];
        }
#pragma unroll
        for (int n = 0; n < 4; n++) {
            int col = n0 + wn * 32 + n * 8 + 2 * j;
            float b0 = bias[col], b1 = bias[col + 1];
            float v00 = acc[i][n][0] + b0, v01 = acc[i][n][1] + b1;
            float v10 = acc[i][n][2] + b0, v11 = acc[i][n][3] + b1;
            if (out_half) {
                uint32_t* Cu = (uint32_t*)C;
                Cu[(size_t)r_lo * 128 + (col >> 1)]       = pk_f16x2(v00 * oscale, v01 * oscale);
                Cu[(size_t)(r_lo + 8) * 128 + (col >> 1)] = pk_f16x2(v10 * oscale, v11 * oscale);
            } else {
                float s0 = sw[col * 3], s1 = sw[col * 3 + 1], s2 = sw[col * 3 + 2];
                float t0 = sw[(col+1) * 3], t1 = sw[(col+1) * 3 + 1], t2 = sw[(col+1) * 3 + 2];
                v00 += p0a * s0 + p1a * s1 + p2a * s2 + sb[col];
                v01 += p0a * t0 + p1a * t1 + p2a * t2 + sb[col + 1];
                v10 += p0b * s0 + p1b * s1 + p2b * s2 + sb[col];
                v11 += p0b * t0 + p1b * t1 + p2b * t2 + sb[col + 1];
                float* Cf = (float*)C;
                *(float2*)&Cf[(size_t)r_lo * 256 + col]       = make_float2(v00, v01);
                *(float2*)&Cf[(size_t)(r_lo + 8) * 256 + col] = make_float2(v10, v11);
            }
        }
    }
}

// ---- merged Q/K/V projection: one launch, 640 blocks ----
__global__ void __launch_bounds__(256, 2)
gemm_qkv_mma(const uint32_t* __restrict__ Aq,
             const uint32_t* __restrict__ Akv,
             const float* __restrict__ in_w,
             const float* __restrict__ in_b,
             uint32_t* __restrict__ Cq,
             uint32_t* __restrict__ Ck,
             uint32_t* __restrict__ Cv,
             float qscale)
{
    extern __shared__ uint32_t hsm[];
    int id = blockIdx.x;
    const uint32_t* A; const float* W; const float* bias;
    uint32_t* C; float os;
    int t;
    if (id < 128) {
        t = id;       A = Aq;  W = in_w;             bias = in_b;       C = Cq; os = qscale;
    } else if (id < 384) {
        t = id - 128; A = Akv; W = in_w + 256*256;   bias = in_b + 256; C = Ck; os = 1.0f;
    } else {
        t = id - 384; A = Akv; W = in_w + 512*256;   bias = in_b + 512; C = Cv; os = 1.0f;
    }
    gemm_f16_body(hsm, A, W, bias, C, 1, os, nullptr, nullptr, nullptr,
                  (t >> 2) * 128, (t & 3) * 64);
}

// ---- output projection (f16 MMA, A = packed attention) + spatial ----
__global__ void __launch_bounds__(256, 2)
gemm_out_mma(const uint32_t* __restrict__ A,
             const float* __restrict__ W,
             const float* __restrict__ bias,
             float* __restrict__ C,
             const float* __restrict__ pts,
             const float* __restrict__ sw,
             const float* __restrict__ sb)
{
    extern __shared__ uint32_t hsm[];
    gemm_f16_body(hsm, A, W, bias, C, 0, 1.0f, pts, sw, sb,
                  blockIdx.x * 128, blockIdx.y * 64);
}

// =====================================================================
// Kernel 4: flash attention — kv-split 8 warps (round-15 config) with
// occ 2 (reg target 128) and packed-f16 output.
// =====================================================================
#define KV32 20
#define VV32 40
#define SMEM_K_OFF(buf) ((buf) * (128 * KV32))
#define SMEM_V_OFF(buf) (2 * 128 * KV32 + (buf) * (64 * VV32))
#define FLASH_SMEM_U32 (2 * 128 * KV32 + 2 * 64 * VV32)

__global__ void __launch_bounds__(256, 2)
flash_mma_kernel(const uint32_t* __restrict__ Q, const uint32_t* __restrict__ K,
                 const uint32_t* __restrict__ V, uint32_t* __restrict__ O)
{
    extern __shared__ uint32_t smu[];

    int tid = threadIdx.x;
    int wid = tid >> 5, lane = tid & 31;
    int g = lane >> 2, j = lane & 3;
    int wg = wid >> 2, w4 = wid & 3;
    int q0 = blockIdx.x * 128;
    int bh = blockIdx.y, b = bh >> 3, h = bh & 7;

    const uint32_t* qp = Q + ((size_t)b * NQ + q0 + w4 * 32) * 128 + h * 16;
    const uint32_t* kp = K + (size_t)b * LK * 128 + h * 16;
    const uint32_t* vp = V + (size_t)b * LK * 128 + h * 16;

    uint32_t aq[2][2][4];
#pragma unroll
    for (int i = 0; i < 2; i++)
#pragma unroll
        for (int kt = 0; kt < 2; kt++) {
            int rb = i * 16;
            aq[i][kt][0] = qp[(size_t)(rb + g) * 128 + kt * 8 + j];
            aq[i][kt][1] = qp[(size_t)(rb + g + 8) * 128 + kt * 8 + j];
            aq[i][kt][2] = qp[(size_t)(rb + g) * 128 + kt * 8 + j + 4];
            aq[i][kt][3] = qp[(size_t)(rb + g + 8) * 128 + kt * 8 + j + 4];
        }

    float o[2][4][4];
#pragma unroll
    for (int i = 0; i < 2; i++)
#pragma unroll
        for (int n = 0; n < 4; n++)
#pragma unroll
            for (int r = 0; r < 4; r++) o[i][n][r] = 0.0f;
    float lacc[2][4] = {{0,0,0,0},{0,0,0,0}};

    int krow[2], kq4[2];
#pragma unroll
    for (int u = 0; u < 2; u++) {
        int fid = tid + 256 * u;
        krow[u] = fid >> 2;
        kq4[u]  = (fid & 3) * 4;
    }
    int vpi = tid >> 2, vqq = (tid & 3) * 4;

    uint4 kpre[2], ve, vo;
#pragma unroll
    for (int u = 0; u < 2; u++)
        kpre[u] = *(const uint4*)&kp[(size_t)krow[u] * 128 + kq4[u]];
    ve = *(const uint4*)&vp[(size_t)(2 * vpi) * 128 + vqq];
    vo = *(const uint4*)&vp[(size_t)(2 * vpi + 1) * 128 + vqq];

#pragma unroll
    for (int u = 0; u < 2; u++)
        *(uint4*)&smu[SMEM_K_OFF(0) + krow[u] * KV32 + kq4[u]] = kpre[u];
    {
        uint4 w0, w1;
        w0.x = prmt(ve.x, vo.x, 0x5410); w0.y = prmt(ve.x, vo.x, 0x7632);
        w0.z = prmt(ve.y, vo.y, 0x5410); w0.w = prmt(ve.y, vo.y, 0x7632);
        w1.x = prmt(ve.z, vo.z, 0x5410); w1.y = prmt(ve.z, vo.z, 0x7632);
        w1.z = prmt(ve.w, vo.w, 0x5410); w1.w = prmt(ve.w, vo.w, 0x7632);
        *(uint4*)&smu[SMEM_V_OFF(0) + vpi * VV32 + vqq * 2]     = w0;
        *(uint4*)&smu[SMEM_V_OFF(0) + vpi * VV32 + vqq * 2 + 4] = w1;
    }

    for (int c = 0; c < 32; c++) {
        int buf = c & 1;
        if (c < 31) {
            int kb = (c + 1) * 128;
#pragma unroll
            for (int u = 0; u < 2; u++)
                kpre[u] = *(const uint4*)&kp[(size_t)(kb + krow[u]) * 128 + kq4[u]];
            ve = *(const uint4*)&vp[(size_t)(kb + 2 * vpi) * 128 + vqq];
            vo = *(const uint4*)&vp[(size_t)(kb + 2 * vpi + 1) * 128 + vqq];
        }
        __syncthreads();

        const uint32_t* Ks = &smu[SMEM_K_OFF(buf)];
        const uint32_t* Vs = &smu[SMEM_V_OFF(buf)];

#pragma unroll
        for (int qq = 0; qq < 2; qq++) {
            float s[2][4][4];
#pragma unroll
            for (int i = 0; i < 2; i++)
#pragma unroll
                for (int nt = 0; nt < 4; nt++)
#pragma unroll
                    for (int r = 0; r < 4; r++) s[i][nt][r] = 0.0f;

#pragma unroll
            for (int kt = 0; kt < 2; kt++) {
#pragma unroll
                for (int nt = 0; nt < 4; nt++) {
                    int kvrow = wg * 64 + qq * 32 + nt * 8 + g;
                    uint32_t b0 = Ks[kvrow * KV32 + kt * 8 + j];
                    uint32_t b1 = Ks[kvrow * KV32 + kt * 8 + j + 4];
#pragma unroll
                    for (int i = 0; i < 2; i++)
                        mma_f16(s[i][nt][0], s[i][nt][1], s[i][nt][2], s[i][nt][3],
                                aq[i][kt][0], aq[i][kt][1], aq[i][kt][2], aq[i][kt][3],
                                b0, b1);
                }
            }

#pragma unroll
            for (int t = 0; t < 2; t++) {
                uint32_t pa[2][4];
#pragma unroll
                for (int i = 0; i < 2; i++) {
                    pa[i][0] = ex2_f16x2(pk_f16x2(s[i][2*t][0],   s[i][2*t][1]));
                    pa[i][1] = ex2_f16x2(pk_f16x2(s[i][2*t][2],   s[i][2*t][3]));
                    pa[i][2] = ex2_f16x2(pk_f16x2(s[i][2*t+1][0], s[i][2*t+1][1]));
                    pa[i][3] = ex2_f16x2(pk_f16x2(s[i][2*t+1][2], s[i][2*t+1][3]));
                    mma_f16(lacc[i][0], lacc[i][1], lacc[i][2], lacc[i][3],
                            pa[i][0], pa[i][1], pa[i][2], pa[i][3], ONESH2, ONESH2);
                }

                int pairbase = wg * 32 + (qq * 2 + t) * 8;
#pragma unroll
                for (int no = 0; no < 4; no++) {
                    uint32_t b0 = Vs[(pairbase + j)     * VV32 + no * 8 + g];
                    uint32_t b1 = Vs[(pairbase + j + 4) * VV32 + no * 8 + g];
#pragma unroll
                    for (int i = 0; i < 2; i++)
                        mma_f16(o[i][no][0], o[i][no][1], o[i][no][2], o[i][no][3],
                                pa[i][0], pa[i][1], pa[i][2], pa[i][3], b0, b1);
                }
            }
        }

        if (c < 31) {
            int nb = 1 - buf;
#pragma unroll
            for (int u = 0; u < 2; u++)
                *(uint4*)&smu[SMEM_K_OFF(nb) + krow[u] * KV32 + kq4[u]] = kpre[u];
            uint4 w0, w1;
            w0.x = prmt(ve.x, vo.x, 0x5410); w0.y = prmt(ve.x, vo.x, 0x7632);
            w0.z = prmt(ve.y, vo.y, 0x5410); w0.w = prmt(ve.y, vo.y, 0x7632);
            w1.x = prmt(ve.z, vo.z, 0x5410); w1.y = prmt(ve.z, vo.z, 0x7632);
            w1.z = prmt(ve.w, vo.w, 0x5410); w1.w = prmt(ve.w, vo.w, 0x7632);
            *(uint4*)&smu[SMEM_V_OFF(nb) + vpi * VV32 + vqq * 2]     = w0;
            *(uint4*)&smu[SMEM_V_OFF(nb) + vpi * VV32 + vqq * 2 + 4] = w1;
        }
    }

    // ---- combine the two kv-half partials via smem (reuse staging) ----
    __syncthreads();
    float* osm = (float*)smu;
    int slot = (tid & 127) * 36;
    if (wg == 1) {
#pragma unroll
        for (int i = 0; i < 2; i++)
#pragma unroll
            for (int no = 0; no < 4; no++)
#pragma unroll
                for (int r = 0; r < 4; r++)
                    osm[slot + (i * 4 + no) * 4 + r] = o[i][no][r];
        osm[slot + 32] = lacc[0][0];
        osm[slot + 33] = lacc[0][2];
        osm[slot + 34] = lacc[1][0];
        osm[slot + 35] = lacc[1][2];
    }
    __syncthreads();
    if (wg == 0) {
#pragma unroll
        for (int i = 0; i < 2; i++) {
            float l0 = lacc[i][0] + osm[slot + 32 + i * 2];
            float l1 = lacc[i][2] + osm[slot + 33 + i * 2];
            float inv0 = 1.0f / l0, inv1 = 1.0f / l1;
            uint32_t* op = O + ((size_t)b * NQ + q0 + w4 * 32 + i * 16) * 128 + h * 16;
#pragma unroll
            for (int no = 0; no < 4; no++) {
                int col = no * 8 + 2 * j;     // even
                float v0 = o[i][no][0] + osm[slot + (i * 4 + no) * 4 + 0];
                float v1 = o[i][no][1] + osm[slot + (i * 4 + no) * 4 + 1];
                float v2 = o[i][no][2] + osm[slot + (i * 4 + no) * 4 + 2];
                float v3 = o[i][no][3] + osm[slot + (i * 4 + no) * 4 + 3];
                op[(size_t)g * 128 + (col >> 1)]       = pk_f16x2(v0 * inv0, v1 * inv0);
                op[(size_t)(g + 8) * 128 + (col >> 1)] = pk_f16x2(v2 * inv1, v3 * inv1);
            }
        }
    }
}

// =====================================================================
// Launch
// =====================================================================
extern "C" void kernel_launch(void* const* d_in, const int* in_sizes, int n_in,
                              void* d_out, int out_size)
{
    const float* cur_pts = (const float*)d_in[0];
    const float* cur_f   = (const float*)d_in[1];
    const float* nbr_pts = (const float*)d_in[2];
    const float* nbr_f   = (const float*)d_in[3];
    const float* in_w    = (const float*)d_in[4];
    const float* in_b    = (const float*)d_in[5];
    const float* out_w   = (const float*)d_in[6];
    const float* out_b   = (const float*)d_in[7];
    const float* sw      = (const float*)d_in[8];
    const float* sb      = (const float*)d_in[9];
    float* out = (float*)d_out;

    uint32_t *dq, *dk, *dv, *dce, *dan, *dat;
    cudaGetSymbolAddress((void**)&dq,  g_q);
    cudaGetSymbolAddress((void**)&dk,  g_k);
    cudaGetSymbolAddress((void**)&dv,  g_v);
    cudaGetSymbolAddress((void**)&dce, g_cur_edge);
    cudaGetSymbolAddress((void**)&dan, g_all_nbr);
    cudaGetSymbolAddress((void**)&dat, g_attn);

    int flash_smem = FLASH_SMEM_U32 * (int)sizeof(uint32_t);
    int qkv_smem   = QKV_SMEM_U32 * (int)sizeof(uint32_t);
    static int attr_set = 0;
    if (!attr_set) {
        cudaFuncSetAttribute(flash_mma_kernel,
                             cudaFuncAttributeMaxDynamicSharedMemorySize, flash_smem);
        cudaFuncSetAttribute(gemm_qkv_mma,
                             cudaFuncAttributeMaxDynamicSharedMemorySize, qkv_smem);
        cudaFuncSetAttribute(gemm_out_mma,
                             cudaFuncAttributeMaxDynamicSharedMemorySize, qkv_smem);
        attr_set = 1;
    }

    // scale folded into Q so P = 2^S in flash: (1/sqrt(32)) * log2(e)
    const float QSCALE = 0.25503488f;

    knn_topk_kernel<<<dim3(NQ / 64, NSETS), 128>>>(cur_pts, nbr_pts);
    edge_feats_kernel<<<NSETS * NQ, 128>>>(cur_f, nbr_f);

    gemm_qkv_mma<<<640, 256, qkv_smem>>>(dce, dan, in_w, in_b, dq, dk, dv, QSCALE);

    flash_mma_kernel<<<dim3(NQ / 128, BB * HH), 256, flash_smem>>>(dq, dk, dv, dat);

    gemm_out_mma<<<dim3((BB * NQ) / 128, 4), 256, qkv_smem>>>(
        dat, out_w, out_b, out, cur_pts, sw, sb);
}